// round 9
// baseline (speedup 1.0000x reference)
#include <cuda_runtime.h>
#include <cuda_fp16.h>
#include <math.h>

#define NMAX   50000
#define EMAX   800000
#define EMBED  256
#define HIDDEN 128
#define OUTD   512
#define NCT    32

// ---------------- scratch (static device globals; no allocation) ------------
__device__ __half d_x_lr[(size_t)NMAX * 2 * HIDDEN];  // x_l | x_r per row, fp16
__device__ float d_h[(size_t)NMAX * HIDDEN];
__device__ int   d_ct[NMAX];
__device__ int   d_count[NMAX];
__device__ int   d_offs[NMAX + 1];
__device__ int   d_cursor[NMAX];
__device__ int   d_srcs[EMAX];                        // src node ids in dst-CSR order
__device__ float d_Wlr[EMBED * 2 * HIDDEN];           // concat(W_l,W_r), tf32-rounded
__device__ float d_blr[2 * HIDDEN];
__device__ float d_spT[NCT * OUTD];

// ---------------- helpers ----------------------------------------------------
__device__ __forceinline__ float eluf(float x)   { return x > 0.f ? x : expm1f(x); }
__device__ __forceinline__ float lreluf(float x) { return x > 0.f ? x : 0.2f * x; }
__device__ __forceinline__ float softplusf(float x) {
    return fmaxf(x, 0.f) + log1pf(expf(-fabsf(x)));
}
__device__ __forceinline__ float tf32r(float x) {
    float o;
    asm("cvt.rna.tf32.f32 %0, %1;" : "=f"(o) : "f"(x));
    return o;
}
__device__ __forceinline__ void mma_tf32(float& c0, float& c1, float& c2, float& c3,
                                         unsigned a0, unsigned a1, unsigned a2, unsigned a3,
                                         unsigned b0, unsigned b1) {
    asm("mma.sync.aligned.m16n8k8.row.col.f32.tf32.tf32.f32 "
        "{%0,%1,%2,%3},{%4,%5,%6,%7},{%8,%9},{%0,%1,%2,%3};"
        : "+f"(c0), "+f"(c1), "+f"(c2), "+f"(c3)
        : "r"(a0), "r"(a1), "r"(a2), "r"(a3), "r"(b0), "r"(b1));
}
__device__ __forceinline__ float4 h4_to_f4(uint2 u) {
    __half2 a = *(__half2*)&u.x;
    __half2 b = *(__half2*)&u.y;
    float2 fa = __half22float2(a);
    float2 fb = __half22float2(b);
    return make_float4(fa.x, fa.y, fb.x, fb.y);
}

// ---------------- tiny prep kernels -----------------------------------------
__global__ void k_ct(const float* __restrict__ onehot, int N) {
    int i = blockIdx.x * blockDim.x + threadIdx.x;
    if (i >= N) return;
    float best = -1e30f; int bi = 0;
    #pragma unroll
    for (int j = 0; j < NCT; j++) {
        float v = onehot[(size_t)i * NCT + j];
        if (v > best) { best = v; bi = j; }
    }
    d_ct[i] = bi;
}

__global__ void k_zero(int N) {
    int i = blockIdx.x * blockDim.x + threadIdx.x;
    if (i < N) d_count[i] = 0;
}

__global__ void k_asm(const float* __restrict__ W_l, const float* __restrict__ b_l,
                      const float* __restrict__ W_r, const float* __restrict__ b_r,
                      const float* __restrict__ dispersion) {
    int idx = blockIdx.x * blockDim.x + threadIdx.x;
    if (idx < EMBED * 2 * HIDDEN) {
        int k = idx >> 8;
        int j = idx & 255;
        float v = (j < HIDDEN) ? W_l[k * HIDDEN + j] : W_r[k * HIDDEN + (j - HIDDEN)];
        d_Wlr[idx] = tf32r(v);
    }
    if (idx < 2 * HIDDEN)
        d_blr[idx] = (idx < HIDDEN) ? b_l[idx] : b_r[idx - HIDDEN];
    if (idx < NCT * OUTD) {
        int ct = idx / OUTD, o = idx % OUTD;
        d_spT[idx] = softplusf(dispersion[o * NCT + ct]);
    }
}

// ---------------- CSR build --------------------------------------------------
__global__ void k_hist(const int* __restrict__ ei, int E) {
    int e = blockIdx.x * blockDim.x + threadIdx.x;
    if (e >= E) return;
    atomicAdd(&d_count[ei[E + e]], 1);
}

__global__ void k_scan(int N) {
    __shared__ int part[1024];
    int t = threadIdx.x;
    int chunk = (N + 1023) / 1024;
    int b = t * chunk;
    int e = min(b + chunk, N);
    int s = 0;
    for (int i = b; i < e; i++) s += d_count[i];
    part[t] = s;
    __syncthreads();
    for (int d = 1; d < 1024; d <<= 1) {
        int v = (t >= d) ? part[t - d] : 0;
        __syncthreads();
        part[t] += v;
        __syncthreads();
    }
    int run = (t == 0) ? 0 : part[t - 1];
    for (int i = b; i < e; i++) {
        d_offs[i] = run;
        d_cursor[i] = run;
        run += d_count[i];
    }
    if (e == N) d_offs[N] = run;
}

__global__ void k_scatter(const int* __restrict__ ei, int E) {
    int e = blockIdx.x * blockDim.x + threadIdx.x;
    if (e >= E) return;
    int s = ei[e];
    int d = ei[E + e];
    int pos = atomicAdd(&d_cursor[d], 1);
    d_srcs[pos] = s;
}

// ---------------- fused edge phase: one warp per dst, 2 edges in flight -------
// softmax identity: no max-shift needed (logits tiny). fp16 x_lr rows.
// Two independent shfl-reduce chains per iteration overlap their latency.
// All gather indices clamped to end-1 (always finite); validity via al masks.
__global__ void k_edge(const float* __restrict__ att, const float* __restrict__ gat_bias,
                       int N) {
    int warp = (blockIdx.x * blockDim.x + threadIdx.x) >> 5;
    int lane = threadIdx.x & 31;
    if (warp >= N) return;
    int start = d_offs[warp];
    int end   = d_offs[warp + 1];

    const uint2* x2 = (const uint2*)d_x_lr;   // row = 64 uint2 (32 x_l + 32 x_r)
    float4 xr = h4_to_f4(x2[(size_t)warp * 64 + 32 + lane]);
    float4 a  = ((const float4*)att)[lane];

    float4 acc = make_float4(0.f, 0.f, 0.f, 0.f);
    float denom = 0.f;

    if (start < end) {
        int last = end - 1;
        uint2 r0 = x2[(size_t)d_srcs[start] * 64 + lane];
        uint2 r1 = x2[(size_t)d_srcs[min(start + 1, last)] * 64 + lane];
        for (int i = start; i < end; i += 2) {
            uint2 n0, n1;
            if (i + 2 < end) {
                n0 = x2[(size_t)d_srcs[i + 2] * 64 + lane];
                n1 = x2[(size_t)d_srcs[min(i + 3, last)] * 64 + lane];
            }
            float4 xl0 = h4_to_f4(r0);
            float4 xl1 = h4_to_f4(r1);
            float p0 = lreluf(xl0.x + xr.x) * a.x
                     + lreluf(xl0.y + xr.y) * a.y
                     + lreluf(xl0.z + xr.z) * a.z
                     + lreluf(xl0.w + xr.w) * a.w;
            float p1 = lreluf(xl1.x + xr.x) * a.x
                     + lreluf(xl1.y + xr.y) * a.y
                     + lreluf(xl1.z + xr.z) * a.z
                     + lreluf(xl1.w + xr.w) * a.w;
            #pragma unroll
            for (int o = 16; o; o >>= 1) {
                p0 += __shfl_xor_sync(0xffffffffu, p0, o);
                p1 += __shfl_xor_sync(0xffffffffu, p1, o);
            }
            float al0 = __expf(p0);
            float al1 = (i + 1 < end) ? __expf(p1) : 0.f;
            acc.x = fmaf(al0, xl0.x, fmaf(al1, xl1.x, acc.x));
            acc.y = fmaf(al0, xl0.y, fmaf(al1, xl1.y, acc.y));
            acc.z = fmaf(al0, xl0.z, fmaf(al1, xl1.z, acc.z));
            acc.w = fmaf(al0, xl0.w, fmaf(al1, xl1.w, acc.w));
            denom += al0 + al1;
            r0 = n0;
            r1 = n1;
        }
    }
    float inv = 1.f / (denom + 1e-16f);
    float4 gb = ((const float4*)gat_bias)[lane];
    float4 hv;
    hv.x = eluf(fmaf(acc.x, inv, gb.x));
    hv.y = eluf(fmaf(acc.y, inv, gb.y));
    hv.z = eluf(fmaf(acc.z, inv, gb.z));
    hv.w = eluf(fmaf(acc.w, inv, gb.w));
    ((float4*)d_h)[(size_t)warp * 32 + lane] = hv;
}

// ---------------- tf32 tensor-core GEMM -------------------------------------
// F16_OUT: epilogue packs each adjacent col pair into __half2.
template<bool FUSE_EMB, bool PRE_TF32, bool F16_OUT>
__global__ __launch_bounds__(256) void k_gemm_mma(
    int M, int K, int Nout,
    const float* __restrict__ A, const float* __restrict__ B,
    const float* __restrict__ bias, void* __restrict__ Cout,
    const float* __restrict__ W_embed, const float* __restrict__ b_embed,
    const float* __restrict__ lds)
{
    __shared__ float As[128 * 36];
    __shared__ float Bs[32 * 132];
    int tid  = threadIdx.x;
    int lane = tid & 31;
    int wid  = tid >> 5;
    int wm   = (wid >> 2) * 64;
    int wn   = (wid & 3) * 32;
    int m0 = blockIdx.x * 128;
    int n0 = blockIdx.y * 128;

    float acc[4][4][4];
    #pragma unroll
    for (int i = 0; i < 4; i++)
        #pragma unroll
        for (int j = 0; j < 4; j++)
            #pragma unroll
            for (int r = 0; r < 4; r++) acc[i][j][r] = 0.f;

    int a_c = (tid & 7) * 4;
    int a_r = tid >> 3;
    int b_c = (tid & 31) * 4;
    int b_r = tid >> 5;

    int fr = lane >> 2;
    int fc = lane & 3;

    for (int k0 = 0; k0 < K; k0 += 32) {
        #pragma unroll
        for (int rr = a_r; rr < 128; rr += 32) {
            int row = m0 + rr;
            float4 v = make_float4(0.f, 0.f, 0.f, 0.f);
            if (row < M) {
                if (FUSE_EMB) {
                    int ct = d_ct[row];
                    float l = lds[row];
                    int kk = k0 + a_c;
                    float4 we = *(const float4*)&W_embed[ct * EMBED + kk];
                    float4 wl = *(const float4*)&W_embed[NCT * EMBED + kk];
                    float4 be = *(const float4*)&b_embed[kk];
                    v.x = eluf(fmaf(l, wl.x, we.x) + be.x);
                    v.y = eluf(fmaf(l, wl.y, we.y) + be.y);
                    v.z = eluf(fmaf(l, wl.z, we.z) + be.z);
                    v.w = eluf(fmaf(l, wl.w, we.w) + be.w);
                } else {
                    v = *(const float4*)&A[(size_t)row * K + k0 + a_c];
                }
                v.x = tf32r(v.x); v.y = tf32r(v.y);
                v.z = tf32r(v.z); v.w = tf32r(v.w);
            }
            *(float4*)&As[rr * 36 + a_c] = v;
        }
        #pragma unroll
        for (int rr = b_r; rr < 32; rr += 8) {
            float4 v = *(const float4*)&B[(size_t)(k0 + rr) * Nout + n0 + b_c];
            if (!PRE_TF32) {
                v.x = tf32r(v.x); v.y = tf32r(v.y);
                v.z = tf32r(v.z); v.w = tf32r(v.w);
            }
            *(float4*)&Bs[rr * 132 + b_c] = v;
        }
        __syncthreads();

        #pragma unroll
        for (int kk = 0; kk < 32; kk += 8) {
            unsigned af[4][4];
            #pragma unroll
            for (int i = 0; i < 4; i++) {
                int row = wm + i * 16 + fr;
                af[i][0] = __float_as_uint(As[(row    ) * 36 + kk + fc    ]);
                af[i][1] = __float_as_uint(As[(row + 8) * 36 + kk + fc    ]);
                af[i][2] = __float_as_uint(As[(row    ) * 36 + kk + fc + 4]);
                af[i][3] = __float_as_uint(As[(row + 8) * 36 + kk + fc + 4]);
            }
            unsigned bf[4][2];
            #pragma unroll
            for (int j = 0; j < 4; j++) {
                int col = wn + j * 8 + fr;
                bf[j][0] = __float_as_uint(Bs[(kk + fc    ) * 132 + col]);
                bf[j][1] = __float_as_uint(Bs[(kk + fc + 4) * 132 + col]);
            }
            #pragma unroll
            for (int i = 0; i < 4; i++)
                #pragma unroll
                for (int j = 0; j < 4; j++)
                    mma_tf32(acc[i][j][0], acc[i][j][1], acc[i][j][2], acc[i][j][3],
                             af[i][0], af[i][1], af[i][2], af[i][3],
                             bf[j][0], bf[j][1]);
        }
        __syncthreads();
    }

    #pragma unroll
    for (int j = 0; j < 4; j++) {
        int col = n0 + wn + j * 8 + fc * 2;
        float2 bb = *(const float2*)&bias[col];
        #pragma unroll
        for (int i = 0; i < 4; i++) {
            int row = m0 + wm + i * 16 + fr;
            if (row < M) {
                float2 o0 = make_float2(acc[i][j][0] + bb.x, acc[i][j][1] + bb.y);
                if (F16_OUT)
                    *(__half2*)&((__half*)Cout)[(size_t)row * Nout + col] =
                        __float22half2_rn(o0);
                else
                    *(float2*)&((float*)Cout)[(size_t)row * Nout + col] = o0;
            }
            if (row + 8 < M) {
                float2 o1 = make_float2(acc[i][j][2] + bb.x, acc[i][j][3] + bb.y);
                if (F16_OUT)
                    *(__half2*)&((__half*)Cout)[(size_t)(row + 8) * Nout + col] =
                        __float22half2_rn(o1);
                else
                    *(float2*)&((float*)Cout)[(size_t)(row + 8) * Nout + col] = o1;
            }
        }
    }
}

// ---------------- dispersion output: table gather -----------------------------
__global__ void k_disp(float* __restrict__ out2, int N) {
    int idx = blockIdx.x * blockDim.x + threadIdx.x;
    if (idx >= N * (OUTD / 4)) return;
    int i = idx >> 7;
    int o = idx & 127;
    ((float4*)out2)[idx] = ((const float4*)d_spT)[d_ct[i] * 128 + o];
}

// ---------------- launch ------------------------------------------------------
extern "C" void kernel_launch(void* const* d_in, const int* in_sizes, int n_in,
                              void* d_out, int out_size) {
    const float* onehot  = (const float*)d_in[0];
    const float* lds     = (const float*)d_in[1];
    const int*   ei      = (const int*)  d_in[2];
    const float* W_embed = (const float*)d_in[3];
    const float* b_embed = (const float*)d_in[4];
    const float* W_l     = (const float*)d_in[5];
    const float* b_l     = (const float*)d_in[6];
    const float* W_r     = (const float*)d_in[7];
    const float* b_r     = (const float*)d_in[8];
    const float* att     = (const float*)d_in[9];
    const float* gbias   = (const float*)d_in[10];
    const float* W_out   = (const float*)d_in[11];
    const float* b_out   = (const float*)d_in[12];
    const float* disper  = (const float*)d_in[13];

    int N = in_sizes[1];
    int E = in_sizes[2] / 2;

    static bool inited = false;
    static cudaStream_t s1, s2;
    static cudaEvent_t evRoot, evPrep, evCSR, evDisp;
    if (!inited) {
        cudaStreamCreateWithFlags(&s1, cudaStreamNonBlocking);
        cudaStreamCreateWithFlags(&s2, cudaStreamNonBlocking);
        cudaEventCreateWithFlags(&evRoot, cudaEventDisableTiming);
        cudaEventCreateWithFlags(&evPrep, cudaEventDisableTiming);
        cudaEventCreateWithFlags(&evCSR,  cudaEventDisableTiming);
        cudaEventCreateWithFlags(&evDisp, cudaEventDisableTiming);
        inited = true;
    }

    void *p_xlr; float *p_h, *p_Wlr, *p_blr;
    cudaGetSymbolAddress(&p_xlr, d_x_lr);
    cudaGetSymbolAddress((void**)&p_h,    d_h);
    cudaGetSymbolAddress((void**)&p_Wlr,  d_Wlr);
    cudaGetSymbolAddress((void**)&p_blr,  d_blr);

    float* out_logits = (float*)d_out;
    float* out_disp   = (float*)d_out + (size_t)N * OUTD;

    // fork: CSR build on s1 (independent of node features)
    cudaEventRecord(evRoot, 0);
    cudaStreamWaitEvent(s1, evRoot, 0);
    k_zero<<<(N + 255) / 256, 256, 0, s1>>>(N);
    k_hist<<<(E + 255) / 256, 256, 0, s1>>>(ei, E);
    k_scan<<<1, 1024, 0, s1>>>(N);
    k_scatter<<<(E + 255) / 256, 256, 0, s1>>>(ei, E);
    cudaEventRecord(evCSR, s1);

    // main stream: prep
    k_ct<<<(N + 255) / 256, 256>>>(onehot, N);
    k_asm<<<(EMBED * 2 * HIDDEN + 255) / 256, 256>>>(W_l, b_l, W_r, b_r, disper);
    cudaEventRecord(evPrep, 0);

    // s2: dispersion output (needs only ct + spT)
    cudaStreamWaitEvent(s2, evPrep, 0);
    k_disp<<<(N * (OUTD / 4) + 255) / 256, 256, 0, s2>>>(out_disp, N);
    cudaEventRecord(evDisp, s2);

    // main: fused embedding + dual transform GEMM -> fp16 x_lr
    k_gemm_mma<true, true, true><<<dim3((N + 127) / 128, (2 * HIDDEN) / 128), 256>>>(
        N, EMBED, 2 * HIDDEN, nullptr, p_Wlr, p_blr, p_xlr, W_embed, b_embed, lds);

    // join CSR, run fused single-pass edge phase
    cudaStreamWaitEvent(0, evCSR, 0);
    k_edge<<<(N * 32 + 255) / 256, 256>>>(att, gbias, N);

    // output head (fp32 out)
    k_gemm_mma<false, false, false><<<dim3((N + 127) / 128, OUTD / 128), 256>>>(
        N, HIDDEN, OUTD, p_h, W_out, b_out, out_logits, nullptr, nullptr, nullptr);

    // join disp
    cudaStreamWaitEvent(0, evDisp, 0);
}

// round 10
// speedup vs baseline: 1.3002x; 1.3002x over previous
#include <cuda_runtime.h>
#include <cuda_fp16.h>
#include <math.h>

#define NMAX   50000
#define EMAX   800000
#define EMBED  256
#define HIDDEN 128
#define OUTD   512
#define NCT    32

// ---------------- scratch (static device globals; no allocation) ------------
__device__ __half d_x_lr[(size_t)NMAX * 2 * HIDDEN];  // x_l | x_r per row, fp16
__device__ __half d_h[(size_t)NMAX * HIDDEN];         // fp16
__device__ int   d_ct[NMAX];
__device__ int   d_count[NMAX];
__device__ int   d_offs[NMAX + 1];
__device__ int   d_cursor[NMAX];
__device__ int   d_srcs[EMAX];                        // src node ids in dst-CSR order
__device__ __half d_WlrT[2 * HIDDEN * EMBED];         // [n=256][k=256] fp16 (W_l|W_r)^T
__device__ __half d_WoutT[OUTD * HIDDEN];             // [n=512][k=128] fp16 W_out^T
__device__ float d_blr[2 * HIDDEN];
__device__ float d_spT[NCT * OUTD];

// ---------------- helpers ----------------------------------------------------
__device__ __forceinline__ float eluf(float x)   { return x > 0.f ? x : expm1f(x); }
__device__ __forceinline__ float lreluf(float x) { return x > 0.f ? x : 0.2f * x; }
__device__ __forceinline__ float softplusf(float x) {
    return fmaxf(x, 0.f) + log1pf(expf(-fabsf(x)));
}
__device__ __forceinline__ void mma_f16(float& c0, float& c1, float& c2, float& c3,
                                        unsigned a0, unsigned a1, unsigned a2, unsigned a3,
                                        unsigned b0, unsigned b1) {
    asm("mma.sync.aligned.m16n8k16.row.col.f32.f16.f16.f32 "
        "{%0,%1,%2,%3},{%4,%5,%6,%7},{%8,%9},{%0,%1,%2,%3};"
        : "+f"(c0), "+f"(c1), "+f"(c2), "+f"(c3)
        : "r"(a0), "r"(a1), "r"(a2), "r"(a3), "r"(b0), "r"(b1));
}
__device__ __forceinline__ float4 h4_to_f4(uint2 u) {
    __half2 a = *(__half2*)&u.x;
    __half2 b = *(__half2*)&u.y;
    float2 fa = __half22float2(a);
    float2 fb = __half22float2(b);
    return make_float4(fa.x, fa.y, fb.x, fb.y);
}
__device__ __forceinline__ unsigned pack_h2(float lo, float hi) {
    __half2 h = __floats2half2_rn(lo, hi);
    return *(unsigned*)&h;
}

// ---------------- tiny prep kernels -----------------------------------------
__global__ void k_ct(const float* __restrict__ onehot, int N) {
    int i = blockIdx.x * blockDim.x + threadIdx.x;
    if (i >= N) return;
    float best = -1e30f; int bi = 0;
    #pragma unroll
    for (int j = 0; j < NCT; j++) {
        float v = onehot[(size_t)i * NCT + j];
        if (v > best) { best = v; bi = j; }
    }
    d_ct[i] = bi;
}

__global__ void k_zero(int N) {
    int i = blockIdx.x * blockDim.x + threadIdx.x;
    if (i < N) d_count[i] = 0;
}

__global__ void k_asm(const float* __restrict__ W_l, const float* __restrict__ b_l,
                      const float* __restrict__ W_r, const float* __restrict__ b_r,
                      const float* __restrict__ W_out, const float* __restrict__ dispersion) {
    int idx = blockIdx.x * blockDim.x + threadIdx.x;
    if (idx < 2 * HIDDEN * EMBED) {          // WlrT [j=256][k=256]
        int j = idx >> 8;
        int k = idx & 255;
        float v = (j < HIDDEN) ? W_l[k * HIDDEN + j] : W_r[k * HIDDEN + (j - HIDDEN)];
        d_WlrT[idx] = __float2half(v);
    }
    if (idx < OUTD * HIDDEN) {               // WoutT [j=512][k=128]
        int j = idx >> 7;
        int k = idx & 127;
        d_WoutT[idx] = __float2half(W_out[k * OUTD + j]);
    }
    if (idx < 2 * HIDDEN)
        d_blr[idx] = (idx < HIDDEN) ? b_l[idx] : b_r[idx - HIDDEN];
    if (idx < NCT * OUTD) {
        int ct = idx / OUTD, o = idx % OUTD;
        d_spT[idx] = softplusf(dispersion[o * NCT + ct]);
    }
}

// ---------------- CSR build --------------------------------------------------
__global__ void k_hist(const int* __restrict__ ei, int E) {
    int e = blockIdx.x * blockDim.x + threadIdx.x;
    if (e >= E) return;
    atomicAdd(&d_count[ei[E + e]], 1);
}

__global__ void k_scan(int N) {
    __shared__ int part[1024];
    int t = threadIdx.x;
    int chunk = (N + 1023) / 1024;
    int b = t * chunk;
    int e = min(b + chunk, N);
    int s = 0;
    for (int i = b; i < e; i++) s += d_count[i];
    part[t] = s;
    __syncthreads();
    for (int d = 1; d < 1024; d <<= 1) {
        int v = (t >= d) ? part[t - d] : 0;
        __syncthreads();
        part[t] += v;
        __syncthreads();
    }
    int run = (t == 0) ? 0 : part[t - 1];
    for (int i = b; i < e; i++) {
        d_offs[i] = run;
        d_cursor[i] = run;
        run += d_count[i];
    }
    if (e == N) d_offs[N] = run;
}

__global__ void k_scatter(const int* __restrict__ ei, int E) {
    int e = blockIdx.x * blockDim.x + threadIdx.x;
    if (e >= E) return;
    int s = ei[e];
    int d = ei[E + e];
    int pos = atomicAdd(&d_cursor[d], 1);
    d_srcs[pos] = s;
}

// ---------------- fused edge phase (proven R6 form, fp16 in/out) --------------
__global__ void k_edge(const float* __restrict__ att, const float* __restrict__ gat_bias,
                       int N) {
    int warp = (blockIdx.x * blockDim.x + threadIdx.x) >> 5;
    int lane = threadIdx.x & 31;
    if (warp >= N) return;
    int start = d_offs[warp];
    int end   = d_offs[warp + 1];

    const uint2* x2 = (const uint2*)d_x_lr;   // row = 64 uint2 (32 x_l + 32 x_r)
    float4 xr = h4_to_f4(x2[(size_t)warp * 64 + 32 + lane]);
    float4 a  = ((const float4*)att)[lane];

    float4 acc = make_float4(0.f, 0.f, 0.f, 0.f);
    float denom = 0.f;

    if (start < end) {
        uint2 raw = x2[(size_t)d_srcs[start] * 64 + lane];
        for (int i = start; i < end; i++) {
            uint2 rawn;
            if (i + 1 < end)
                rawn = x2[(size_t)d_srcs[i + 1] * 64 + lane];
            float4 xl = h4_to_f4(raw);
            float p = lreluf(xl.x + xr.x) * a.x
                    + lreluf(xl.y + xr.y) * a.y
                    + lreluf(xl.z + xr.z) * a.z
                    + lreluf(xl.w + xr.w) * a.w;
            #pragma unroll
            for (int o = 16; o; o >>= 1) p += __shfl_xor_sync(0xffffffffu, p, o);
            float al = __expf(p);
            acc.x = fmaf(al, xl.x, acc.x);
            acc.y = fmaf(al, xl.y, acc.y);
            acc.z = fmaf(al, xl.z, acc.z);
            acc.w = fmaf(al, xl.w, acc.w);
            denom += al;
            raw = rawn;
        }
    }
    float inv = 1.f / (denom + 1e-16f);
    float4 gb = ((const float4*)gat_bias)[lane];
    uint2 st;
    st.x = pack_h2(eluf(fmaf(acc.x, inv, gb.x)), eluf(fmaf(acc.y, inv, gb.y)));
    st.y = pack_h2(eluf(fmaf(acc.z, inv, gb.z)), eluf(fmaf(acc.w, inv, gb.w)));
    ((uint2*)d_h)[(size_t)warp * 32 + lane] = st;
}

// ---------------- fp16 HMMA GEMM: C = op(A)[M,K] @ BT[Nout,K]^T + bias --------
// 128x128 block tile, 8 warps 2(m)x4(n), warp tile 64x32, m16n8k16 4x4 frags.
// As/Bs: half [128][40] (pad 40 -> all frag LDS 32-bank distinct).
// F16_OUT: epilogue packs col pairs into __half2.
template<bool FUSE_EMB, bool F16_OUT>
__global__ __launch_bounds__(256) void k_gemm_h(
    int M, int K, int Nout,
    const __half* __restrict__ A, const __half* __restrict__ BT,
    const float* __restrict__ bias, void* __restrict__ Cout,
    const float* __restrict__ W_embed, const float* __restrict__ b_embed,
    const float* __restrict__ lds)
{
    __shared__ __half As[128 * 40];
    __shared__ __half Bs[128 * 40];
    int tid  = threadIdx.x;
    int lane = tid & 31;
    int wid  = tid >> 5;
    int wm   = (wid >> 2) * 64;
    int wn   = (wid & 3) * 32;
    int m0 = blockIdx.x * 128;
    int n0 = blockIdx.y * 128;

    float acc[4][4][4];
    #pragma unroll
    for (int i = 0; i < 4; i++)
        #pragma unroll
        for (int j = 0; j < 4; j++)
            #pragma unroll
            for (int r = 0; r < 4; r++) acc[i][j][r] = 0.f;

    int ld_r = tid >> 2;          // 0..63
    int ld_c = (tid & 3) * 8;     // half offset within 32-chunk

    int fr = lane >> 2;           // 0..7
    int fc = lane & 3;            // 0..3

    for (int k0 = 0; k0 < K; k0 += 32) {
        // A tile: rows m0+ld_r, m0+ld_r+64 ; 8 halves each
        #pragma unroll
        for (int u = 0; u < 2; u++) {
            int rr = ld_r + u * 64;
            int row = m0 + rr;
            uint4 pk = make_uint4(0, 0, 0, 0);
            if (row < M) {
                if (FUSE_EMB) {
                    int ct = d_ct[row];
                    float l = lds[row];
                    int kk = k0 + ld_c;
                    float4 we0 = *(const float4*)&W_embed[ct * EMBED + kk];
                    float4 we1 = *(const float4*)&W_embed[ct * EMBED + kk + 4];
                    float4 wl0 = *(const float4*)&W_embed[NCT * EMBED + kk];
                    float4 wl1 = *(const float4*)&W_embed[NCT * EMBED + kk + 4];
                    float4 be0 = *(const float4*)&b_embed[kk];
                    float4 be1 = *(const float4*)&b_embed[kk + 4];
                    pk.x = pack_h2(eluf(fmaf(l, wl0.x, we0.x) + be0.x),
                                   eluf(fmaf(l, wl0.y, we0.y) + be0.y));
                    pk.y = pack_h2(eluf(fmaf(l, wl0.z, we0.z) + be0.z),
                                   eluf(fmaf(l, wl0.w, we0.w) + be0.w));
                    pk.z = pack_h2(eluf(fmaf(l, wl1.x, we1.x) + be1.x),
                                   eluf(fmaf(l, wl1.y, we1.y) + be1.y));
                    pk.w = pack_h2(eluf(fmaf(l, wl1.z, we1.z) + be1.z),
                                   eluf(fmaf(l, wl1.w, we1.w) + be1.w));
                } else {
                    pk = *(const uint4*)&A[(size_t)row * K + k0 + ld_c];
                }
            }
            *(uint4*)&As[rr * 40 + ld_c] = pk;
        }
        // B tile: BT rows n0+ld_r, +64 (always valid: Nout multiple of 128)
        #pragma unroll
        for (int u = 0; u < 2; u++) {
            int rr = ld_r + u * 64;
            uint4 pk = *(const uint4*)&BT[(size_t)(n0 + rr) * K + k0 + ld_c];
            *(uint4*)&Bs[rr * 40 + ld_c] = pk;
        }
        __syncthreads();

        #pragma unroll
        for (int kk = 0; kk < 32; kk += 16) {
            unsigned af[4][4];
            #pragma unroll
            for (int i = 0; i < 4; i++) {
                int row = wm + i * 16 + fr;
                af[i][0] = *(const unsigned*)&As[(row    ) * 40 + kk + 2 * fc    ];
                af[i][1] = *(const unsigned*)&As[(row + 8) * 40 + kk + 2 * fc    ];
                af[i][2] = *(const unsigned*)&As[(row    ) * 40 + kk + 2 * fc + 8];
                af[i][3] = *(const unsigned*)&As[(row + 8) * 40 + kk + 2 * fc + 8];
            }
            unsigned bf[4][2];
            #pragma unroll
            for (int j = 0; j < 4; j++) {
                int col = wn + j * 8 + fr;
                bf[j][0] = *(const unsigned*)&Bs[col * 40 + kk + 2 * fc    ];
                bf[j][1] = *(const unsigned*)&Bs[col * 40 + kk + 2 * fc + 8];
            }
            #pragma unroll
            for (int i = 0; i < 4; i++)
                #pragma unroll
                for (int j = 0; j < 4; j++)
                    mma_f16(acc[i][j][0], acc[i][j][1], acc[i][j][2], acc[i][j][3],
                            af[i][0], af[i][1], af[i][2], af[i][3],
                            bf[j][0], bf[j][1]);
        }
        __syncthreads();
    }

    #pragma unroll
    for (int j = 0; j < 4; j++) {
        int col = n0 + wn + j * 8 + fc * 2;
        float2 bb = *(const float2*)&bias[col];
        #pragma unroll
        for (int i = 0; i < 4; i++) {
            int row = m0 + wm + i * 16 + fr;
            if (row < M) {
                float2 o0 = make_float2(acc[i][j][0] + bb.x, acc[i][j][1] + bb.y);
                if (F16_OUT) {
                    unsigned p = pack_h2(o0.x, o0.y);
                    *(unsigned*)&((__half*)Cout)[(size_t)row * Nout + col] = p;
                } else {
                    *(float2*)&((float*)Cout)[(size_t)row * Nout + col] = o0;
                }
            }
            if (row + 8 < M) {
                float2 o1 = make_float2(acc[i][j][2] + bb.x, acc[i][j][3] + bb.y);
                if (F16_OUT) {
                    unsigned p = pack_h2(o1.x, o1.y);
                    *(unsigned*)&((__half*)Cout)[(size_t)(row + 8) * Nout + col] = p;
                } else {
                    *(float2*)&((float*)Cout)[(size_t)(row + 8) * Nout + col] = o1;
                }
            }
        }
    }
}

// ---------------- dispersion output: table gather -----------------------------
__global__ void k_disp(float* __restrict__ out2, int N) {
    int idx = blockIdx.x * blockDim.x + threadIdx.x;
    if (idx >= N * (OUTD / 4)) return;
    int i = idx >> 7;
    int o = idx & 127;
    ((float4*)out2)[idx] = ((const float4*)d_spT)[d_ct[i] * 128 + o];
}

// ---------------- launch ------------------------------------------------------
extern "C" void kernel_launch(void* const* d_in, const int* in_sizes, int n_in,
                              void* d_out, int out_size) {
    const float* onehot  = (const float*)d_in[0];
    const float* lds     = (const float*)d_in[1];
    const int*   ei      = (const int*)  d_in[2];
    const float* W_embed = (const float*)d_in[3];
    const float* b_embed = (const float*)d_in[4];
    const float* W_l     = (const float*)d_in[5];
    const float* b_l     = (const float*)d_in[6];
    const float* W_r     = (const float*)d_in[7];
    const float* b_r     = (const float*)d_in[8];
    const float* att     = (const float*)d_in[9];
    const float* gbias   = (const float*)d_in[10];
    const float* W_out   = (const float*)d_in[11];
    const float* b_out   = (const float*)d_in[12];
    const float* disper  = (const float*)d_in[13];

    int N = in_sizes[1];
    int E = in_sizes[2] / 2;

    static bool inited = false;
    static cudaStream_t s1, s2;
    static cudaEvent_t evRoot, evPrep, evCSR, evDisp;
    if (!inited) {
        cudaStreamCreateWithFlags(&s1, cudaStreamNonBlocking);
        cudaStreamCreateWithFlags(&s2, cudaStreamNonBlocking);
        cudaEventCreateWithFlags(&evRoot, cudaEventDisableTiming);
        cudaEventCreateWithFlags(&evPrep, cudaEventDisableTiming);
        cudaEventCreateWithFlags(&evCSR,  cudaEventDisableTiming);
        cudaEventCreateWithFlags(&evDisp, cudaEventDisableTiming);
        inited = true;
    }

    void *p_xlr, *p_h;
    __half *p_WlrT, *p_WoutT;
    float *p_blr;
    cudaGetSymbolAddress(&p_xlr, d_x_lr);
    cudaGetSymbolAddress(&p_h,   d_h);
    cudaGetSymbolAddress((void**)&p_WlrT,  d_WlrT);
    cudaGetSymbolAddress((void**)&p_WoutT, d_WoutT);
    cudaGetSymbolAddress((void**)&p_blr,   d_blr);

    float* out_logits = (float*)d_out;
    float* out_disp   = (float*)d_out + (size_t)N * OUTD;

    // fork: CSR build on s1 (independent of node features)
    cudaEventRecord(evRoot, 0);
    cudaStreamWaitEvent(s1, evRoot, 0);
    k_zero<<<(N + 255) / 256, 256, 0, s1>>>(N);
    k_hist<<<(E + 255) / 256, 256, 0, s1>>>(ei, E);
    k_scan<<<1, 1024, 0, s1>>>(N);
    k_scatter<<<(E + 255) / 256, 256, 0, s1>>>(ei, E);
    cudaEventRecord(evCSR, s1);

    // main stream: prep
    k_ct<<<(N + 255) / 256, 256>>>(onehot, N);
    k_asm<<<(2 * HIDDEN * EMBED + 255) / 256, 256>>>(W_l, b_l, W_r, b_r, W_out, disper);
    cudaEventRecord(evPrep, 0);

    // s2: dispersion output (needs only ct + spT)
    cudaStreamWaitEvent(s2, evPrep, 0);
    k_disp<<<(N * (OUTD / 4) + 255) / 256, 256, 0, s2>>>(out_disp, N);
    cudaEventRecord(evDisp, s2);

    // main: fused embedding + dual transform GEMM (fp16 HMMA) -> fp16 x_lr
    k_gemm_h<true, true><<<dim3((N + 127) / 128, (2 * HIDDEN) / 128), 256>>>(
        N, EMBED, 2 * HIDDEN, nullptr, p_WlrT, p_blr, p_xlr, W_embed, b_embed, lds);

    // join CSR, run fused single-pass edge phase
    cudaStreamWaitEvent(0, evCSR, 0);
    k_edge<<<(N * 32 + 255) / 256, 256>>>(att, gbias, N);

    // output head (fp16 HMMA, fp32 out)
    k_gemm_h<false, false><<<dim3((N + 127) / 128, OUTD / 128), 256>>>(
        N, HIDDEN, OUTD, (const __half*)p_h, p_WoutT, b_out, out_logits,
        nullptr, nullptr, nullptr);

    // join disp
    cudaStreamWaitEvent(0, evDisp, 0);
}

// round 11
// speedup vs baseline: 1.3496x; 1.0380x over previous
#include <cuda_runtime.h>
#include <cuda_fp16.h>
#include <math.h>

#define NMAX   50000
#define EMAX   800000
#define EMBED  256
#define HIDDEN 128
#define OUTD   512
#define NCT    32

// ---------------- scratch (static device globals; no allocation) ------------
__device__ __half d_x_lr[(size_t)NMAX * 2 * HIDDEN];  // x_l | x_r per row, fp16
__device__ __half d_h[(size_t)NMAX * HIDDEN];         // fp16
__device__ int   d_ct[NMAX];
__device__ int   d_count[NMAX];
__device__ int   d_offs[NMAX + 1];
__device__ int   d_cursor[NMAX];
__device__ int   d_srcs[EMAX];                        // src node ids in dst-CSR order
__device__ __half d_WlrT[2 * HIDDEN * EMBED];         // [n=256][k=256] fp16 (W_l|W_r)^T
__device__ __half d_WoutT[OUTD * HIDDEN];             // [n=512][k=128] fp16 W_out^T
__device__ float d_blr[2 * HIDDEN];
__device__ float d_spT[NCT * OUTD];

// ---------------- helpers ----------------------------------------------------
__device__ __forceinline__ float eluf(float x)   { return x > 0.f ? x : expm1f(x); }
__device__ __forceinline__ float lreluf(float x) { return x > 0.f ? x : 0.2f * x; }
__device__ __forceinline__ float softplusf(float x) {
    return fmaxf(x, 0.f) + log1pf(expf(-fabsf(x)));
}
__device__ __forceinline__ void mma_f16(float& c0, float& c1, float& c2, float& c3,
                                        unsigned a0, unsigned a1, unsigned a2, unsigned a3,
                                        unsigned b0, unsigned b1) {
    asm("mma.sync.aligned.m16n8k16.row.col.f32.f16.f16.f32 "
        "{%0,%1,%2,%3},{%4,%5,%6,%7},{%8,%9},{%0,%1,%2,%3};"
        : "+f"(c0), "+f"(c1), "+f"(c2), "+f"(c3)
        : "r"(a0), "r"(a1), "r"(a2), "r"(a3), "r"(b0), "r"(b1));
}
__device__ __forceinline__ float4 h4_to_f4(uint2 u) {
    __half2 a = *(__half2*)&u.x;
    __half2 b = *(__half2*)&u.y;
    float2 fa = __half22float2(a);
    float2 fb = __half22float2(b);
    return make_float4(fa.x, fa.y, fb.x, fb.y);
}
__device__ __forceinline__ unsigned pack_h2(float lo, float hi) {
    __half2 h = __floats2half2_rn(lo, hi);
    return *(unsigned*)&h;
}

// ---------------- tiny prep kernels -----------------------------------------
__global__ void k_ct(const float* __restrict__ onehot, int N) {
    int i = blockIdx.x * blockDim.x + threadIdx.x;
    if (i >= N) return;
    float best = -1e30f; int bi = 0;
    #pragma unroll
    for (int j = 0; j < NCT; j++) {
        float v = onehot[(size_t)i * NCT + j];
        if (v > best) { best = v; bi = j; }
    }
    d_ct[i] = bi;
}

__global__ void k_zero(int N) {
    int i = blockIdx.x * blockDim.x + threadIdx.x;
    if (i < N) d_count[i] = 0;
}

__global__ void k_asm(const float* __restrict__ W_l, const float* __restrict__ b_l,
                      const float* __restrict__ W_r, const float* __restrict__ b_r,
                      const float* __restrict__ W_out, const float* __restrict__ dispersion) {
    int idx = blockIdx.x * blockDim.x + threadIdx.x;
    if (idx < 2 * HIDDEN * EMBED) {          // WlrT [j=256][k=256]
        int j = idx >> 8;
        int k = idx & 255;
        float v = (j < HIDDEN) ? W_l[k * HIDDEN + j] : W_r[k * HIDDEN + (j - HIDDEN)];
        d_WlrT[idx] = __float2half(v);
    }
    if (idx < OUTD * HIDDEN) {               // WoutT [j=512][k=128]
        int j = idx >> 7;
        int k = idx & 127;
        d_WoutT[idx] = __float2half(W_out[k * OUTD + j]);
    }
    if (idx < 2 * HIDDEN)
        d_blr[idx] = (idx < HIDDEN) ? b_l[idx] : b_r[idx - HIDDEN];
    if (idx < NCT * OUTD) {
        int ct = idx / OUTD, o = idx % OUTD;
        d_spT[idx] = softplusf(dispersion[o * NCT + ct]);
    }
}

// ---------------- CSR build --------------------------------------------------
__global__ void k_hist(const int* __restrict__ ei, int E) {
    int e = blockIdx.x * blockDim.x + threadIdx.x;
    if (e >= E) return;
    atomicAdd(&d_count[ei[E + e]], 1);
}

// smem-resident exclusive scan: counts staged in dynamic smem (coalesced),
// chunk sums + Hillis-Steele over 1024 partials, coalesced write-back.
__global__ void k_scan(int N) {
    extern __shared__ int sc[];
    __shared__ int part[1024];
    int t = threadIdx.x;
    for (int i = t; i < N; i += 1024) sc[i] = d_count[i];
    __syncthreads();
    int chunk = (N + 1023) / 1024;
    int b = t * chunk;
    int e = min(b + chunk, N);
    int s = 0;
    for (int i = b; i < e; i++) s += sc[i];
    part[t] = s;
    __syncthreads();
    for (int d = 1; d < 1024; d <<= 1) {
        int v = (t >= d) ? part[t - d] : 0;
        __syncthreads();
        part[t] += v;
        __syncthreads();
    }
    int run = (t == 0) ? 0 : part[t - 1];
    for (int i = b; i < e; i++) {
        int c = sc[i];
        sc[i] = run;
        run += c;
    }
    __syncthreads();
    for (int i = t; i < N; i += 1024) {
        int v = sc[i];
        d_offs[i] = v;
        d_cursor[i] = v;
    }
    if (t == 1023) d_offs[N] = run;   // run of last thread = total E
}

__global__ void k_scatter(const int* __restrict__ ei, int E) {
    int e = blockIdx.x * blockDim.x + threadIdx.x;
    if (e >= E) return;
    int s = ei[e];
    int d = ei[E + e];
    int pos = atomicAdd(&d_cursor[d], 1);
    d_srcs[pos] = s;
}

// ---------------- fused edge phase (proven form, fp16 in/out) ------------------
__global__ void k_edge(const float* __restrict__ att, const float* __restrict__ gat_bias,
                       int N) {
    int warp = (blockIdx.x * blockDim.x + threadIdx.x) >> 5;
    int lane = threadIdx.x & 31;
    if (warp >= N) return;
    int start = d_offs[warp];
    int end   = d_offs[warp + 1];

    const uint2* x2 = (const uint2*)d_x_lr;   // row = 64 uint2 (32 x_l + 32 x_r)
    float4 xr = h4_to_f4(x2[(size_t)warp * 64 + 32 + lane]);
    float4 a  = ((const float4*)att)[lane];

    float4 acc = make_float4(0.f, 0.f, 0.f, 0.f);
    float denom = 0.f;

    if (start < end) {
        uint2 raw = x2[(size_t)d_srcs[start] * 64 + lane];
        for (int i = start; i < end; i++) {
            uint2 rawn;
            if (i + 1 < end)
                rawn = x2[(size_t)d_srcs[i + 1] * 64 + lane];
            float4 xl = h4_to_f4(raw);
            float p = lreluf(xl.x + xr.x) * a.x
                    + lreluf(xl.y + xr.y) * a.y
                    + lreluf(xl.z + xr.z) * a.z
                    + lreluf(xl.w + xr.w) * a.w;
            #pragma unroll
            for (int o = 16; o; o >>= 1) p += __shfl_xor_sync(0xffffffffu, p, o);
            float al = __expf(p);
            acc.x = fmaf(al, xl.x, acc.x);
            acc.y = fmaf(al, xl.y, acc.y);
            acc.z = fmaf(al, xl.z, acc.z);
            acc.w = fmaf(al, xl.w, acc.w);
            denom += al;
            raw = rawn;
        }
    }
    float inv = 1.f / (denom + 1e-16f);
    float4 gb = ((const float4*)gat_bias)[lane];
    uint2 st;
    st.x = pack_h2(eluf(fmaf(acc.x, inv, gb.x)), eluf(fmaf(acc.y, inv, gb.y)));
    st.y = pack_h2(eluf(fmaf(acc.z, inv, gb.z)), eluf(fmaf(acc.w, inv, gb.w)));
    ((uint2*)d_h)[(size_t)warp * 32 + lane] = st;
}

// ---------------- fp16 HMMA GEMM: C = op(A)[M,K] @ BT[Nout,K]^T + bias --------
template<bool FUSE_EMB, bool F16_OUT>
__global__ __launch_bounds__(256) void k_gemm_h(
    int M, int K, int Nout,
    const __half* __restrict__ A, const __half* __restrict__ BT,
    const float* __restrict__ bias, void* __restrict__ Cout,
    const float* __restrict__ W_embed, const float* __restrict__ b_embed,
    const float* __restrict__ lds)
{
    __shared__ __half As[128 * 40];
    __shared__ __half Bs[128 * 40];
    int tid  = threadIdx.x;
    int lane = tid & 31;
    int wid  = tid >> 5;
    int wm   = (wid >> 2) * 64;
    int wn   = (wid & 3) * 32;
    int m0 = blockIdx.x * 128;
    int n0 = blockIdx.y * 128;

    float acc[4][4][4];
    #pragma unroll
    for (int i = 0; i < 4; i++)
        #pragma unroll
        for (int j = 0; j < 4; j++)
            #pragma unroll
            for (int r = 0; r < 4; r++) acc[i][j][r] = 0.f;

    int ld_r = tid >> 2;
    int ld_c = (tid & 3) * 8;

    int fr = lane >> 2;
    int fc = lane & 3;

    for (int k0 = 0; k0 < K; k0 += 32) {
        #pragma unroll
        for (int u = 0; u < 2; u++) {
            int rr = ld_r + u * 64;
            int row = m0 + rr;
            uint4 pk = make_uint4(0, 0, 0, 0);
            if (row < M) {
                if (FUSE_EMB) {
                    int ct = d_ct[row];
                    float l = lds[row];
                    int kk = k0 + ld_c;
                    float4 we0 = *(const float4*)&W_embed[ct * EMBED + kk];
                    float4 we1 = *(const float4*)&W_embed[ct * EMBED + kk + 4];
                    float4 wl0 = *(const float4*)&W_embed[NCT * EMBED + kk];
                    float4 wl1 = *(const float4*)&W_embed[NCT * EMBED + kk + 4];
                    float4 be0 = *(const float4*)&b_embed[kk];
                    float4 be1 = *(const float4*)&b_embed[kk + 4];
                    pk.x = pack_h2(eluf(fmaf(l, wl0.x, we0.x) + be0.x),
                                   eluf(fmaf(l, wl0.y, we0.y) + be0.y));
                    pk.y = pack_h2(eluf(fmaf(l, wl0.z, we0.z) + be0.z),
                                   eluf(fmaf(l, wl0.w, we0.w) + be0.w));
                    pk.z = pack_h2(eluf(fmaf(l, wl1.x, we1.x) + be1.x),
                                   eluf(fmaf(l, wl1.y, we1.y) + be1.y));
                    pk.w = pack_h2(eluf(fmaf(l, wl1.z, we1.z) + be1.z),
                                   eluf(fmaf(l, wl1.w, we1.w) + be1.w));
                } else {
                    pk = *(const uint4*)&A[(size_t)row * K + k0 + ld_c];
                }
            }
            *(uint4*)&As[rr * 40 + ld_c] = pk;
        }
        #pragma unroll
        for (int u = 0; u < 2; u++) {
            int rr = ld_r + u * 64;
            uint4 pk = *(const uint4*)&BT[(size_t)(n0 + rr) * K + k0 + ld_c];
            *(uint4*)&Bs[rr * 40 + ld_c] = pk;
        }
        __syncthreads();

        #pragma unroll
        for (int kk = 0; kk < 32; kk += 16) {
            unsigned af[4][4];
            #pragma unroll
            for (int i = 0; i < 4; i++) {
                int row = wm + i * 16 + fr;
                af[i][0] = *(const unsigned*)&As[(row    ) * 40 + kk + 2 * fc    ];
                af[i][1] = *(const unsigned*)&As[(row + 8) * 40 + kk + 2 * fc    ];
                af[i][2] = *(const unsigned*)&As[(row    ) * 40 + kk + 2 * fc + 8];
                af[i][3] = *(const unsigned*)&As[(row + 8) * 40 + kk + 2 * fc + 8];
            }
            unsigned bf[4][2];
            #pragma unroll
            for (int j = 0; j < 4; j++) {
                int col = wn + j * 8 + fr;
                bf[j][0] = *(const unsigned*)&Bs[col * 40 + kk + 2 * fc    ];
                bf[j][1] = *(const unsigned*)&Bs[col * 40 + kk + 2 * fc + 8];
            }
            #pragma unroll
            for (int i = 0; i < 4; i++)
                #pragma unroll
                for (int j = 0; j < 4; j++)
                    mma_f16(acc[i][j][0], acc[i][j][1], acc[i][j][2], acc[i][j][3],
                            af[i][0], af[i][1], af[i][2], af[i][3],
                            bf[j][0], bf[j][1]);
        }
        __syncthreads();
    }

    #pragma unroll
    for (int j = 0; j < 4; j++) {
        int col = n0 + wn + j * 8 + fc * 2;
        float2 bb = *(const float2*)&bias[col];
        #pragma unroll
        for (int i = 0; i < 4; i++) {
            int row = m0 + wm + i * 16 + fr;
            if (row < M) {
                float2 o0 = make_float2(acc[i][j][0] + bb.x, acc[i][j][1] + bb.y);
                if (F16_OUT) {
                    unsigned p = pack_h2(o0.x, o0.y);
                    *(unsigned*)&((__half*)Cout)[(size_t)row * Nout + col] = p;
                } else {
                    *(float2*)&((float*)Cout)[(size_t)row * Nout + col] = o0;
                }
            }
            if (row + 8 < M) {
                float2 o1 = make_float2(acc[i][j][2] + bb.x, acc[i][j][3] + bb.y);
                if (F16_OUT) {
                    unsigned p = pack_h2(o1.x, o1.y);
                    *(unsigned*)&((__half*)Cout)[(size_t)(row + 8) * Nout + col] = p;
                } else {
                    *(float2*)&((float*)Cout)[(size_t)(row + 8) * Nout + col] = o1;
                }
            }
        }
    }
}

// ---------------- dispersion output: table gather -----------------------------
__global__ void k_disp(float* __restrict__ out2, int N) {
    int idx = blockIdx.x * blockDim.x + threadIdx.x;
    if (idx >= N * (OUTD / 4)) return;
    int i = idx >> 7;
    int o = idx & 127;
    ((float4*)out2)[idx] = ((const float4*)d_spT)[d_ct[i] * 128 + o];
}

// ---------------- launch ------------------------------------------------------
extern "C" void kernel_launch(void* const* d_in, const int* in_sizes, int n_in,
                              void* d_out, int out_size) {
    const float* onehot  = (const float*)d_in[0];
    const float* lds     = (const float*)d_in[1];
    const int*   ei      = (const int*)  d_in[2];
    const float* W_embed = (const float*)d_in[3];
    const float* b_embed = (const float*)d_in[4];
    const float* W_l     = (const float*)d_in[5];
    const float* b_l     = (const float*)d_in[6];
    const float* W_r     = (const float*)d_in[7];
    const float* b_r     = (const float*)d_in[8];
    const float* att     = (const float*)d_in[9];
    const float* gbias   = (const float*)d_in[10];
    const float* W_out   = (const float*)d_in[11];
    const float* b_out   = (const float*)d_in[12];
    const float* disper  = (const float*)d_in[13];

    int N = in_sizes[1];
    int E = in_sizes[2] / 2;
    int scan_smem = (N + 1) * (int)sizeof(int);

    static bool inited = false;
    static cudaStream_t s1, s2;
    static cudaEvent_t evRoot, evPrep, evCSR, evDisp;
    if (!inited) {
        cudaStreamCreateWithFlags(&s1, cudaStreamNonBlocking);
        cudaStreamCreateWithFlags(&s2, cudaStreamNonBlocking);
        cudaEventCreateWithFlags(&evRoot, cudaEventDisableTiming);
        cudaEventCreateWithFlags(&evPrep, cudaEventDisableTiming);
        cudaEventCreateWithFlags(&evCSR,  cudaEventDisableTiming);
        cudaEventCreateWithFlags(&evDisp, cudaEventDisableTiming);
        cudaFuncSetAttribute(k_scan, cudaFuncAttributeMaxDynamicSharedMemorySize,
                             (NMAX + 1) * (int)sizeof(int));
        inited = true;
    }

    void *p_xlr, *p_h;
    __half *p_WlrT, *p_WoutT;
    float *p_blr;
    cudaGetSymbolAddress(&p_xlr, d_x_lr);
    cudaGetSymbolAddress(&p_h,   d_h);
    cudaGetSymbolAddress((void**)&p_WlrT,  d_WlrT);
    cudaGetSymbolAddress((void**)&p_WoutT, d_WoutT);
    cudaGetSymbolAddress((void**)&p_blr,   d_blr);

    float* out_logits = (float*)d_out;
    float* out_disp   = (float*)d_out + (size_t)N * OUTD;

    cudaEventRecord(evRoot, 0);
    cudaStreamWaitEvent(s1, evRoot, 0);

    // launches 1-2: main prep
    k_ct<<<(N + 255) / 256, 256>>>(onehot, N);
    k_asm<<<(2 * HIDDEN * EMBED + 255) / 256, 256>>>(W_l, b_l, W_r, b_r, W_out, disper);
    cudaEventRecord(evPrep, 0);

    // launch 3: CSR zero on s1
    k_zero<<<(N + 255) / 256, 256, 0, s1>>>(N);

    // launch 4 (ncu-profiled slot): fused embedding + dual transform GEMM
    k_gemm_h<true, true><<<dim3((N + 127) / 128, (2 * HIDDEN) / 128), 256>>>(
        N, EMBED, 2 * HIDDEN, nullptr, p_WlrT, p_blr, p_xlr, W_embed, b_embed, lds);

    // launches 5-7: rest of CSR build on s1
    k_hist<<<(E + 255) / 256, 256, 0, s1>>>(ei, E);
    k_scan<<<1, 1024, scan_smem, s1>>>(N);
    k_scatter<<<(E + 255) / 256, 256, 0, s1>>>(ei, E);
    cudaEventRecord(evCSR, s1);

    // launch 8: dispersion output on s2
    cudaStreamWaitEvent(s2, evPrep, 0);
    k_disp<<<(N * (OUTD / 4) + 255) / 256, 256, 0, s2>>>(out_disp, N);
    cudaEventRecord(evDisp, s2);

    // launch 9: fused edge phase (after CSR join)
    cudaStreamWaitEvent(0, evCSR, 0);
    k_edge<<<(N * 32 + 255) / 256, 256>>>(att, gbias, N);

    // launch 10: output head
    k_gemm_h<false, false><<<dim3((N + 127) / 128, OUTD / 128), 256>>>(
        N, HIDDEN, OUTD, (const __half*)p_h, p_WoutT, b_out, out_logits,
        nullptr, nullptr, nullptr);

    cudaStreamWaitEvent(0, evDisp, 0);
}

// round 12
// speedup vs baseline: 1.5570x; 1.1537x over previous
#include <cuda_runtime.h>
#include <cuda_fp16.h>
#include <math.h>

#define NMAX   50000
#define EMAX   800000
#define EMBED  256
#define HIDDEN 128
#define OUTD   512
#define NCT    32

// ---------------- scratch (static device globals; no allocation) ------------
__device__ __half d_x_lr[(size_t)NMAX * 2 * HIDDEN];  // x_l | x_r per row, fp16
__device__ __half d_h[(size_t)NMAX * HIDDEN];         // fp16
__device__ int   d_ct[NMAX];
__device__ int   d_count[NMAX];
__device__ int   d_offs[NMAX + 1];
__device__ int   d_cursor[NMAX];
__device__ int   d_srcs[EMAX];                        // src node ids in dst-CSR order
__device__ __half d_WlrT[2 * HIDDEN * EMBED];         // [n=256][k=256] fp16 (W_l|W_r)^T
__device__ __half d_WoutT[OUTD * HIDDEN];             // [n=512][k=128] fp16 W_out^T
__device__ float d_blr[2 * HIDDEN];
__device__ float d_spT[NCT * OUTD];

// ---------------- helpers ----------------------------------------------------
__device__ __forceinline__ float eluf(float x)   { return x > 0.f ? x : __expf(x) - 1.f; }
__device__ __forceinline__ float lreluf(float x) { return x > 0.f ? x : 0.2f * x; }
__device__ __forceinline__ float softplusf(float x) {
    return fmaxf(x, 0.f) + log1pf(expf(-fabsf(x)));
}
__device__ __forceinline__ void mma_f16(float& c0, float& c1, float& c2, float& c3,
                                        unsigned a0, unsigned a1, unsigned a2, unsigned a3,
                                        unsigned b0, unsigned b1) {
    asm("mma.sync.aligned.m16n8k16.row.col.f32.f16.f16.f32 "
        "{%0,%1,%2,%3},{%4,%5,%6,%7},{%8,%9},{%0,%1,%2,%3};"
        : "+f"(c0), "+f"(c1), "+f"(c2), "+f"(c3)
        : "r"(a0), "r"(a1), "r"(a2), "r"(a3), "r"(b0), "r"(b1));
}
__device__ __forceinline__ float4 h4_to_f4(uint2 u) {
    __half2 a = *(__half2*)&u.x;
    __half2 b = *(__half2*)&u.y;
    float2 fa = __half22float2(a);
    float2 fb = __half22float2(b);
    return make_float4(fa.x, fa.y, fb.x, fb.y);
}
__device__ __forceinline__ unsigned pack_h2(float lo, float hi) {
    __half2 h = __floats2half2_rn(lo, hi);
    return *(unsigned*)&h;
}

// ---------------- tiny prep kernels -----------------------------------------
__global__ void k_ct(const float* __restrict__ onehot, int N) {
    int i = blockIdx.x * blockDim.x + threadIdx.x;
    if (i >= N) return;
    float best = -1e30f; int bi = 0;
    #pragma unroll
    for (int j = 0; j < NCT; j++) {
        float v = onehot[(size_t)i * NCT + j];
        if (v > best) { best = v; bi = j; }
    }
    d_ct[i] = bi;
}

__global__ void k_zero(int N) {
    int i = blockIdx.x * blockDim.x + threadIdx.x;
    if (i < N) d_count[i] = 0;
}

__global__ void k_asm(const float* __restrict__ W_l, const float* __restrict__ b_l,
                      const float* __restrict__ W_r, const float* __restrict__ b_r,
                      const float* __restrict__ W_out, const float* __restrict__ dispersion) {
    int idx = blockIdx.x * blockDim.x + threadIdx.x;
    if (idx < 2 * HIDDEN * EMBED) {          // WlrT [j=256][k=256]
        int j = idx >> 8;
        int k = idx & 255;
        float v = (j < HIDDEN) ? W_l[k * HIDDEN + j] : W_r[k * HIDDEN + (j - HIDDEN)];
        d_WlrT[idx] = __float2half(v);
    }
    if (idx < OUTD * HIDDEN) {               // WoutT [j=512][k=128]
        int j = idx >> 7;
        int k = idx & 127;
        d_WoutT[idx] = __float2half(W_out[k * OUTD + j]);
    }
    if (idx < 2 * HIDDEN)
        d_blr[idx] = (idx < HIDDEN) ? b_l[idx] : b_r[idx - HIDDEN];
    if (idx < NCT * OUTD) {
        int ct = idx / OUTD, o = idx % OUTD;
        d_spT[idx] = softplusf(dispersion[o * NCT + ct]);
    }
}

// ---------------- CSR build --------------------------------------------------
__global__ void k_hist(const int* __restrict__ ei, int E) {
    int e = blockIdx.x * blockDim.x + threadIdx.x;
    if (e >= E) return;
    atomicAdd(&d_count[ei[E + e]], 1);
}

__global__ void k_scan(int N) {
    extern __shared__ int sc[];
    __shared__ int part[1024];
    int t = threadIdx.x;
    for (int i = t; i < N; i += 1024) sc[i] = d_count[i];
    __syncthreads();
    int chunk = (N + 1023) / 1024;
    int b = t * chunk;
    int e = min(b + chunk, N);
    int s = 0;
    for (int i = b; i < e; i++) s += sc[i];
    part[t] = s;
    __syncthreads();
    for (int d = 1; d < 1024; d <<= 1) {
        int v = (t >= d) ? part[t - d] : 0;
        __syncthreads();
        part[t] += v;
        __syncthreads();
    }
    int run = (t == 0) ? 0 : part[t - 1];
    for (int i = b; i < e; i++) {
        int c = sc[i];
        sc[i] = run;
        run += c;
    }
    __syncthreads();
    for (int i = t; i < N; i += 1024) {
        int v = sc[i];
        d_offs[i] = v;
        d_cursor[i] = v;
    }
    if (t == 1023) d_offs[N] = run;
}

__global__ void k_scatter(const int* __restrict__ ei, int E) {
    int e = blockIdx.x * blockDim.x + threadIdx.x;
    if (e >= E) return;
    int s = ei[e];
    int d = ei[E + e];
    int pos = atomicAdd(&d_cursor[d], 1);
    d_srcs[pos] = s;
}

// ---------------- fused edge phase (proven form, fp16 in/out) ------------------
__global__ void k_edge(const float* __restrict__ att, const float* __restrict__ gat_bias,
                       int N) {
    int warp = (blockIdx.x * blockDim.x + threadIdx.x) >> 5;
    int lane = threadIdx.x & 31;
    if (warp >= N) return;
    int start = d_offs[warp];
    int end   = d_offs[warp + 1];

    const uint2* x2 = (const uint2*)d_x_lr;
    float4 xr = h4_to_f4(x2[(size_t)warp * 64 + 32 + lane]);
    float4 a  = ((const float4*)att)[lane];

    float4 acc = make_float4(0.f, 0.f, 0.f, 0.f);
    float denom = 0.f;

    if (start < end) {
        uint2 raw = x2[(size_t)d_srcs[start] * 64 + lane];
        for (int i = start; i < end; i++) {
            uint2 rawn;
            if (i + 1 < end)
                rawn = x2[(size_t)d_srcs[i + 1] * 64 + lane];
            float4 xl = h4_to_f4(raw);
            float p = lreluf(xl.x + xr.x) * a.x
                    + lreluf(xl.y + xr.y) * a.y
                    + lreluf(xl.z + xr.z) * a.z
                    + lreluf(xl.w + xr.w) * a.w;
            #pragma unroll
            for (int o = 16; o; o >>= 1) p += __shfl_xor_sync(0xffffffffu, p, o);
            float al = __expf(p);
            acc.x = fmaf(al, xl.x, acc.x);
            acc.y = fmaf(al, xl.y, acc.y);
            acc.z = fmaf(al, xl.z, acc.z);
            acc.w = fmaf(al, xl.w, acc.w);
            denom += al;
            raw = rawn;
        }
    }
    float inv = 1.f / (denom + 1e-16f);
    float4 gb = ((const float4*)gat_bias)[lane];
    uint2 st;
    st.x = pack_h2(eluf(fmaf(acc.x, inv, gb.x)), eluf(fmaf(acc.y, inv, gb.y)));
    st.y = pack_h2(eluf(fmaf(acc.z, inv, gb.z)), eluf(fmaf(acc.w, inv, gb.w)));
    ((uint2*)d_h)[(size_t)warp * 32 + lane] = st;
}

// ---------------- fp16 HMMA GEMM, KT=64: C = op(A)[M,K] @ BT[Nout,K]^T + bias --
// 128x128 block tile, 8 warps 2(m)x4(n), warp tile 64x32, m16n8k16 4x4 frags.
// As/Bs: half [128][72] (frag LDS rows*144B: bank = 4*row+fc -> 32 distinct).
template<bool FUSE_EMB, bool F16_OUT>
__global__ __launch_bounds__(256, 2) void k_gemm_h(
    int M, int K, int Nout,
    const __half* __restrict__ A, const __half* __restrict__ BT,
    const float* __restrict__ bias, void* __restrict__ Cout,
    const float* __restrict__ W_embed, const float* __restrict__ b_embed,
    const float* __restrict__ lds)
{
    __shared__ __half As[128 * 72];
    __shared__ __half Bs[128 * 72];
    int tid  = threadIdx.x;
    int lane = tid & 31;
    int wid  = tid >> 5;
    int wm   = (wid >> 2) * 64;
    int wn   = (wid & 3) * 32;
    int m0 = blockIdx.x * 128;
    int n0 = blockIdx.y * 128;

    float acc[4][4][4];
    #pragma unroll
    for (int i = 0; i < 4; i++)
        #pragma unroll
        for (int j = 0; j < 4; j++)
            #pragma unroll
            for (int r = 0; r < 4; r++) acc[i][j][r] = 0.f;

    int ld_r = tid >> 3;          // 0..31 (4 rows per thread, step 32)
    int ld_c = (tid & 7) * 8;     // 8 halves per load, covers 64

    int fr = lane >> 2;
    int fc = lane & 3;

    // hoist per-row gather state for the fused embedding loader
    int   ctv[4];
    float lv[4];
    bool  okv[4];
    if (FUSE_EMB) {
        #pragma unroll
        for (int u = 0; u < 4; u++) {
            int row = m0 + ld_r + u * 32;
            okv[u] = (row < M);
            ctv[u] = okv[u] ? d_ct[row] : 0;
            lv[u]  = okv[u] ? lds[row] : 0.f;
        }
    }

    for (int k0 = 0; k0 < K; k0 += 64) {
        #pragma unroll
        for (int u = 0; u < 4; u++) {
            int rr = ld_r + u * 32;
            uint4 pk = make_uint4(0, 0, 0, 0);
            if (FUSE_EMB) {
                if (okv[u]) {
                    int ct = ctv[u];
                    float l = lv[u];
                    int kk = k0 + ld_c;
                    float4 we0 = *(const float4*)&W_embed[ct * EMBED + kk];
                    float4 we1 = *(const float4*)&W_embed[ct * EMBED + kk + 4];
                    float4 wl0 = *(const float4*)&W_embed[NCT * EMBED + kk];
                    float4 wl1 = *(const float4*)&W_embed[NCT * EMBED + kk + 4];
                    float4 be0 = *(const float4*)&b_embed[kk];
                    float4 be1 = *(const float4*)&b_embed[kk + 4];
                    pk.x = pack_h2(eluf(fmaf(l, wl0.x, we0.x) + be0.x),
                                   eluf(fmaf(l, wl0.y, we0.y) + be0.y));
                    pk.y = pack_h2(eluf(fmaf(l, wl0.z, we0.z) + be0.z),
                                   eluf(fmaf(l, wl0.w, we0.w) + be0.w));
                    pk.z = pack_h2(eluf(fmaf(l, wl1.x, we1.x) + be1.x),
                                   eluf(fmaf(l, wl1.y, we1.y) + be1.y));
                    pk.w = pack_h2(eluf(fmaf(l, wl1.z, we1.z) + be1.z),
                                   eluf(fmaf(l, wl1.w, we1.w) + be1.w));
                }
            } else {
                int row = m0 + rr;
                if (row < M)
                    pk = *(const uint4*)&A[(size_t)row * K + k0 + ld_c];
            }
            *(uint4*)&As[rr * 72 + ld_c] = pk;
        }
        #pragma unroll
        for (int u = 0; u < 4; u++) {
            int rr = ld_r + u * 32;
            uint4 pk = *(const uint4*)&BT[(size_t)(n0 + rr) * K + k0 + ld_c];
            *(uint4*)&Bs[rr * 72 + ld_c] = pk;
        }
        __syncthreads();

        #pragma unroll
        for (int kk = 0; kk < 64; kk += 16) {
            unsigned af[4][4];
            #pragma unroll
            for (int i = 0; i < 4; i++) {
                int row = wm + i * 16 + fr;
                af[i][0] = *(const unsigned*)&As[(row    ) * 72 + kk + 2 * fc    ];
                af[i][1] = *(const unsigned*)&As[(row + 8) * 72 + kk + 2 * fc    ];
                af[i][2] = *(const unsigned*)&As[(row    ) * 72 + kk + 2 * fc + 8];
                af[i][3] = *(const unsigned*)&As[(row + 8) * 72 + kk + 2 * fc + 8];
            }
            unsigned bf[4][2];
            #pragma unroll
            for (int j = 0; j < 4; j++) {
                int col = wn + j * 8 + fr;
                bf[j][0] = *(const unsigned*)&Bs[col * 72 + kk + 2 * fc    ];
                bf[j][1] = *(const unsigned*)&Bs[col * 72 + kk + 2 * fc + 8];
            }
            #pragma unroll
            for (int i = 0; i < 4; i++)
                #pragma unroll
                for (int j = 0; j < 4; j++)
                    mma_f16(acc[i][j][0], acc[i][j][1], acc[i][j][2], acc[i][j][3],
                            af[i][0], af[i][1], af[i][2], af[i][3],
                            bf[j][0], bf[j][1]);
        }
        __syncthreads();
    }

    #pragma unroll
    for (int j = 0; j < 4; j++) {
        int col = n0 + wn + j * 8 + fc * 2;
        float2 bb = *(const float2*)&bias[col];
        #pragma unroll
        for (int i = 0; i < 4; i++) {
            int row = m0 + wm + i * 16 + fr;
            if (row < M) {
                float2 o0 = make_float2(acc[i][j][0] + bb.x, acc[i][j][1] + bb.y);
                if (F16_OUT) {
                    unsigned p = pack_h2(o0.x, o0.y);
                    *(unsigned*)&((__half*)Cout)[(size_t)row * Nout + col] = p;
                } else {
                    *(float2*)&((float*)Cout)[(size_t)row * Nout + col] = o0;
                }
            }
            if (row + 8 < M) {
                float2 o1 = make_float2(acc[i][j][2] + bb.x, acc[i][j][3] + bb.y);
                if (F16_OUT) {
                    unsigned p = pack_h2(o1.x, o1.y);
                    *(unsigned*)&((__half*)Cout)[(size_t)(row + 8) * Nout + col] = p;
                } else {
                    *(float2*)&((float*)Cout)[(size_t)(row + 8) * Nout + col] = o1;
                }
            }
        }
    }
}

// ---------------- dispersion output: table gather -----------------------------
__global__ void k_disp(float* __restrict__ out2, int N) {
    int idx = blockIdx.x * blockDim.x + threadIdx.x;
    if (idx >= N * (OUTD / 4)) return;
    int i = idx >> 7;
    int o = idx & 127;
    ((float4*)out2)[idx] = ((const float4*)d_spT)[d_ct[i] * 128 + o];
}

// ---------------- launch ------------------------------------------------------
extern "C" void kernel_launch(void* const* d_in, const int* in_sizes, int n_in,
                              void* d_out, int out_size) {
    const float* onehot  = (const float*)d_in[0];
    const float* lds     = (const float*)d_in[1];
    const int*   ei      = (const int*)  d_in[2];
    const float* W_embed = (const float*)d_in[3];
    const float* b_embed = (const float*)d_in[4];
    const float* W_l     = (const float*)d_in[5];
    const float* b_l     = (const float*)d_in[6];
    const float* W_r     = (const float*)d_in[7];
    const float* b_r     = (const float*)d_in[8];
    const float* att     = (const float*)d_in[9];
    const float* gbias   = (const float*)d_in[10];
    const float* W_out   = (const float*)d_in[11];
    const float* b_out   = (const float*)d_in[12];
    const float* disper  = (const float*)d_in[13];

    int N = in_sizes[1];
    int E = in_sizes[2] / 2;
    int scan_smem = (N + 1) * (int)sizeof(int);

    static bool inited = false;
    static cudaStream_t s1, s2;
    static cudaEvent_t evRoot, evPrep, evCSR, evDisp;
    if (!inited) {
        cudaStreamCreateWithFlags(&s1, cudaStreamNonBlocking);
        cudaStreamCreateWithFlags(&s2, cudaStreamNonBlocking);
        cudaEventCreateWithFlags(&evRoot, cudaEventDisableTiming);
        cudaEventCreateWithFlags(&evPrep, cudaEventDisableTiming);
        cudaEventCreateWithFlags(&evCSR,  cudaEventDisableTiming);
        cudaEventCreateWithFlags(&evDisp, cudaEventDisableTiming);
        cudaFuncSetAttribute(k_scan, cudaFuncAttributeMaxDynamicSharedMemorySize,
                             (NMAX + 1) * (int)sizeof(int));
        inited = true;
    }

    void *p_xlr, *p_h;
    __half *p_WlrT, *p_WoutT;
    float *p_blr;
    cudaGetSymbolAddress(&p_xlr, d_x_lr);
    cudaGetSymbolAddress(&p_h,   d_h);
    cudaGetSymbolAddress((void**)&p_WlrT,  d_WlrT);
    cudaGetSymbolAddress((void**)&p_WoutT, d_WoutT);
    cudaGetSymbolAddress((void**)&p_blr,   d_blr);

    float* out_logits = (float*)d_out;
    float* out_disp   = (float*)d_out + (size_t)N * OUTD;

    cudaEventRecord(evRoot, 0);
    cudaStreamWaitEvent(s1, evRoot, 0);

    // launches 1-2: main prep
    k_ct<<<(N + 255) / 256, 256>>>(onehot, N);
    k_asm<<<(2 * HIDDEN * EMBED + 255) / 256, 256>>>(W_l, b_l, W_r, b_r, W_out, disper);
    cudaEventRecord(evPrep, 0);

    // launch 3: CSR zero on s1
    k_zero<<<(N + 255) / 256, 256, 0, s1>>>(N);

    // launch 4 (ncu-profiled slot): fused embedding + dual transform GEMM
    k_gemm_h<true, true><<<dim3((N + 127) / 128, (2 * HIDDEN) / 128), 256>>>(
        N, EMBED, 2 * HIDDEN, nullptr, p_WlrT, p_blr, p_xlr, W_embed, b_embed, lds);

    // launches 5-7: rest of CSR build on s1
    k_hist<<<(E + 255) / 256, 256, 0, s1>>>(ei, E);
    k_scan<<<1, 1024, scan_smem, s1>>>(N);
    k_scatter<<<(E + 255) / 256, 256, 0, s1>>>(ei, E);
    cudaEventRecord(evCSR, s1);

    // launch 8: dispersion output on s2
    cudaStreamWaitEvent(s2, evPrep, 0);
    k_disp<<<(N * (OUTD / 4) + 255) / 256, 256, 0, s2>>>(out_disp, N);
    cudaEventRecord(evDisp, s2);

    // launch 9: fused edge phase (after CSR join)
    cudaStreamWaitEvent(0, evCSR, 0);
    k_edge<<<(N * 32 + 255) / 256, 256>>>(att, gbias, N);

    // launch 10: output head
    k_gemm_h<false, false><<<dim3((N + 127) / 128, OUTD / 128), 256>>>(
        N, HIDDEN, OUTD, (const __half*)p_h, p_WoutT, b_out, out_logits,
        nullptr, nullptr, nullptr);

    cudaStreamWaitEvent(0, evDisp, 0);
}

// round 13
// speedup vs baseline: 1.5892x; 1.0207x over previous
#include <cuda_runtime.h>
#include <cuda_fp16.h>
#include <math.h>

#define NMAX   50000
#define EMAX   800000
#define EMBED  256
#define HIDDEN 128
#define OUTD   512
#define NCT    32

// ---------------- scratch (static device globals; no allocation) ------------
__device__ __half d_x_lr[(size_t)NMAX * 2 * HIDDEN];  // x_l | x_r per row, fp16
__device__ __half d_h[(size_t)NMAX * HIDDEN];         // fp16
__device__ int   d_ct[NMAX];
__device__ int   d_count[NMAX];
__device__ int   d_offs[NMAX + 1];
__device__ int   d_cursor[NMAX];
__device__ int   d_srcs[EMAX];                        // src node ids in dst-CSR order
__device__ __half d_WlrT[2 * HIDDEN * EMBED];         // [n=256][k=256] fp16 (W_l|W_r)^T
__device__ __half d_WoutT[OUTD * HIDDEN];             // [n=512][k=128] fp16 W_out^T
__device__ float d_blr[2 * HIDDEN];
__device__ float d_spT[NCT * OUTD];

// ---------------- helpers ----------------------------------------------------
__device__ __forceinline__ float eluf(float x)   { return x > 0.f ? x : __expf(x) - 1.f; }
__device__ __forceinline__ float lreluf(float x) { return x > 0.f ? x : 0.2f * x; }
__device__ __forceinline__ float softplusf(float x) {
    return fmaxf(x, 0.f) + log1pf(expf(-fabsf(x)));
}
__device__ __forceinline__ void mma_f16(float& c0, float& c1, float& c2, float& c3,
                                        unsigned a0, unsigned a1, unsigned a2, unsigned a3,
                                        unsigned b0, unsigned b1) {
    asm("mma.sync.aligned.m16n8k16.row.col.f32.f16.f16.f32 "
        "{%0,%1,%2,%3},{%4,%5,%6,%7},{%8,%9},{%0,%1,%2,%3};"
        : "+f"(c0), "+f"(c1), "+f"(c2), "+f"(c3)
        : "r"(a0), "r"(a1), "r"(a2), "r"(a3), "r"(b0), "r"(b1));
}
__device__ __forceinline__ void ldsm_x4(unsigned& r0, unsigned& r1,
                                        unsigned& r2, unsigned& r3, unsigned addr) {
    asm volatile("ldmatrix.sync.aligned.m8n8.x4.shared.b16 {%0,%1,%2,%3}, [%4];"
                 : "=r"(r0), "=r"(r1), "=r"(r2), "=r"(r3) : "r"(addr));
}
__device__ __forceinline__ unsigned smem_u32(const void* p) {
    return (unsigned)__cvta_generic_to_shared(p);
}
__device__ __forceinline__ float4 h4_to_f4(uint2 u) {
    __half2 a = *(__half2*)&u.x;
    __half2 b = *(__half2*)&u.y;
    float2 fa = __half22float2(a);
    float2 fb = __half22float2(b);
    return make_float4(fa.x, fa.y, fb.x, fb.y);
}
__device__ __forceinline__ unsigned pack_h2(float lo, float hi) {
    __half2 h = __floats2half2_rn(lo, hi);
    return *(unsigned*)&h;
}

// ---------------- tiny prep kernels -----------------------------------------
__global__ void k_ct(const float* __restrict__ onehot, int N) {
    int i = blockIdx.x * blockDim.x + threadIdx.x;
    if (i >= N) return;
    float best = -1e30f; int bi = 0;
    #pragma unroll
    for (int j = 0; j < NCT; j++) {
        float v = onehot[(size_t)i * NCT + j];
        if (v > best) { best = v; bi = j; }
    }
    d_ct[i] = bi;
}

__global__ void k_zero(int N) {
    int i = blockIdx.x * blockDim.x + threadIdx.x;
    if (i < N) d_count[i] = 0;
}

__global__ void k_asm(const float* __restrict__ W_l, const float* __restrict__ b_l,
                      const float* __restrict__ W_r, const float* __restrict__ b_r,
                      const float* __restrict__ W_out, const float* __restrict__ dispersion) {
    int idx = blockIdx.x * blockDim.x + threadIdx.x;
    if (idx < 2 * HIDDEN * EMBED) {          // WlrT [j=256][k=256]
        int j = idx >> 8;
        int k = idx & 255;
        float v = (j < HIDDEN) ? W_l[k * HIDDEN + j] : W_r[k * HIDDEN + (j - HIDDEN)];
        d_WlrT[idx] = __float2half(v);
    }
    if (idx < OUTD * HIDDEN) {               // WoutT [j=512][k=128]
        int j = idx >> 7;
        int k = idx & 127;
        d_WoutT[idx] = __float2half(W_out[k * OUTD + j]);
    }
    if (idx < 2 * HIDDEN)
        d_blr[idx] = (idx < HIDDEN) ? b_l[idx] : b_r[idx - HIDDEN];
    if (idx < NCT * OUTD) {
        int ct = idx / OUTD, o = idx % OUTD;
        d_spT[idx] = softplusf(dispersion[o * NCT + ct]);
    }
}

// ---------------- CSR build --------------------------------------------------
__global__ void k_hist(const int* __restrict__ ei, int E) {
    int e = blockIdx.x * blockDim.x + threadIdx.x;
    if (e >= E) return;
    atomicAdd(&d_count[ei[E + e]], 1);
}

__global__ void k_scan(int N) {
    extern __shared__ int sc[];
    __shared__ int part[1024];
    int t = threadIdx.x;
    for (int i = t; i < N; i += 1024) sc[i] = d_count[i];
    __syncthreads();
    int chunk = (N + 1023) / 1024;
    int b = t * chunk;
    int e = min(b + chunk, N);
    int s = 0;
    for (int i = b; i < e; i++) s += sc[i];
    part[t] = s;
    __syncthreads();
    for (int d = 1; d < 1024; d <<= 1) {
        int v = (t >= d) ? part[t - d] : 0;
        __syncthreads();
        part[t] += v;
        __syncthreads();
    }
    int run = (t == 0) ? 0 : part[t - 1];
    for (int i = b; i < e; i++) {
        int c = sc[i];
        sc[i] = run;
        run += c;
    }
    __syncthreads();
    for (int i = t; i < N; i += 1024) {
        int v = sc[i];
        d_offs[i] = v;
        d_cursor[i] = v;
    }
    if (t == 1023) d_offs[N] = run;
}

__global__ void k_scatter(const int* __restrict__ ei, int E) {
    int e = blockIdx.x * blockDim.x + threadIdx.x;
    if (e >= E) return;
    int s = ei[e];
    int d = ei[E + e];
    int pos = atomicAdd(&d_cursor[d], 1);
    d_srcs[pos] = s;
}

// ---------------- fused edge phase (proven form, fp16 in/out) ------------------
__global__ void k_edge(const float* __restrict__ att, const float* __restrict__ gat_bias,
                       int N) {
    int warp = (blockIdx.x * blockDim.x + threadIdx.x) >> 5;
    int lane = threadIdx.x & 31;
    if (warp >= N) return;
    int start = d_offs[warp];
    int end   = d_offs[warp + 1];

    const uint2* x2 = (const uint2*)d_x_lr;
    float4 xr = h4_to_f4(x2[(size_t)warp * 64 + 32 + lane]);
    float4 a  = ((const float4*)att)[lane];

    float4 acc = make_float4(0.f, 0.f, 0.f, 0.f);
    float denom = 0.f;

    if (start < end) {
        uint2 raw = x2[(size_t)d_srcs[start] * 64 + lane];
        for (int i = start; i < end; i++) {
            uint2 rawn;
            if (i + 1 < end)
                rawn = x2[(size_t)d_srcs[i + 1] * 64 + lane];
            float4 xl = h4_to_f4(raw);
            float p = lreluf(xl.x + xr.x) * a.x
                    + lreluf(xl.y + xr.y) * a.y
                    + lreluf(xl.z + xr.z) * a.z
                    + lreluf(xl.w + xr.w) * a.w;
            #pragma unroll
            for (int o = 16; o; o >>= 1) p += __shfl_xor_sync(0xffffffffu, p, o);
            float al = __expf(p);
            acc.x = fmaf(al, xl.x, acc.x);
            acc.y = fmaf(al, xl.y, acc.y);
            acc.z = fmaf(al, xl.z, acc.z);
            acc.w = fmaf(al, xl.w, acc.w);
            denom += al;
            raw = rawn;
        }
    }
    float inv = 1.f / (denom + 1e-16f);
    float4 gb = ((const float4*)gat_bias)[lane];
    uint2 st;
    st.x = pack_h2(eluf(fmaf(acc.x, inv, gb.x)), eluf(fmaf(acc.y, inv, gb.y)));
    st.y = pack_h2(eluf(fmaf(acc.z, inv, gb.z)), eluf(fmaf(acc.w, inv, gb.w)));
    ((uint2*)d_h)[(size_t)warp * 32 + lane] = st;
}

// ---------------- fp16 HMMA GEMM, KT=64, ldmatrix frag loads -------------------
// 128x128 block tile, 8 warps 2(m)x4(n), warp tile 64x32, m16n8k16 4x4 frags.
// As/Bs: half [128][72]; LDSM phases conflict-free (144B row stride -> 8 rows
// cover 0..112 in 16B steps).
template<bool FUSE_EMB, bool F16_OUT>
__global__ __launch_bounds__(256, 2) void k_gemm_h(
    int M, int K, int Nout,
    const __half* __restrict__ A, const __half* __restrict__ BT,
    const float* __restrict__ bias, void* __restrict__ Cout,
    const float* __restrict__ W_embed, const float* __restrict__ b_embed,
    const float* __restrict__ lds)
{
    __shared__ __half As[128 * 72];
    __shared__ __half Bs[128 * 72];
    int tid  = threadIdx.x;
    int lane = tid & 31;
    int wid  = tid >> 5;
    int wm   = (wid >> 2) * 64;
    int wn   = (wid & 3) * 32;
    int m0 = blockIdx.x * 128;
    int n0 = blockIdx.y * 128;

    float acc[4][4][4];
    #pragma unroll
    for (int i = 0; i < 4; i++)
        #pragma unroll
        for (int j = 0; j < 4; j++)
            #pragma unroll
            for (int r = 0; r < 4; r++) acc[i][j][r] = 0.f;

    int ld_r = tid >> 3;          // 0..31 (4 rows per thread, step 32)
    int ld_c = (tid & 7) * 8;     // 8 halves per load, covers 64

    int fr = lane >> 2;
    int fc = lane & 3;

    // ldmatrix lane-address bases (bytes into smem), computed once.
    // A groups: g0 (row, k), g1 (row+8, k), g2 (row, k+8), g3 (row+8, k+8)
    // B groups: g0 (colJ, k), g1 (colJ, k+8), g2 (colJ+8, k), g3 (colJ+8, k+8)
    int lrow = lane & 7;
    int g    = lane >> 3;
    unsigned a_base[4], b_base[2];
    #pragma unroll
    for (int i = 0; i < 4; i++)
        a_base[i] = smem_u32(&As[(wm + i * 16 + (g & 1) * 8 + lrow) * 72 + (g >> 1) * 8]);
    #pragma unroll
    for (int jj = 0; jj < 2; jj++)
        b_base[jj] = smem_u32(&Bs[(wn + jj * 16 + (g >> 1) * 8 + lrow) * 72 + (g & 1) * 8]);

    // hoisted per-row gather state for fused embedding loader
    int   ctv[4];
    float lv[4];
    bool  okv[4];
    if (FUSE_EMB) {
        #pragma unroll
        for (int u = 0; u < 4; u++) {
            int row = m0 + ld_r + u * 32;
            okv[u] = (row < M);
            ctv[u] = okv[u] ? d_ct[row] : 0;
            lv[u]  = okv[u] ? lds[row] : 0.f;
        }
    }

    for (int k0 = 0; k0 < K; k0 += 64) {
        #pragma unroll
        for (int u = 0; u < 4; u++) {
            int rr = ld_r + u * 32;
            uint4 pk = make_uint4(0, 0, 0, 0);
            if (FUSE_EMB) {
                if (okv[u]) {
                    int ct = ctv[u];
                    float l = lv[u];
                    int kk = k0 + ld_c;
                    float4 we0 = *(const float4*)&W_embed[ct * EMBED + kk];
                    float4 we1 = *(const float4*)&W_embed[ct * EMBED + kk + 4];
                    float4 wl0 = *(const float4*)&W_embed[NCT * EMBED + kk];
                    float4 wl1 = *(const float4*)&W_embed[NCT * EMBED + kk + 4];
                    float4 be0 = *(const float4*)&b_embed[kk];
                    float4 be1 = *(const float4*)&b_embed[kk + 4];
                    pk.x = pack_h2(eluf(fmaf(l, wl0.x, we0.x) + be0.x),
                                   eluf(fmaf(l, wl0.y, we0.y) + be0.y));
                    pk.y = pack_h2(eluf(fmaf(l, wl0.z, we0.z) + be0.z),
                                   eluf(fmaf(l, wl0.w, we0.w) + be0.w));
                    pk.z = pack_h2(eluf(fmaf(l, wl1.x, we1.x) + be1.x),
                                   eluf(fmaf(l, wl1.y, we1.y) + be1.y));
                    pk.w = pack_h2(eluf(fmaf(l, wl1.z, we1.z) + be1.z),
                                   eluf(fmaf(l, wl1.w, we1.w) + be1.w));
                }
            } else {
                int row = m0 + rr;
                if (row < M)
                    pk = *(const uint4*)&A[(size_t)row * K + k0 + ld_c];
            }
            *(uint4*)&As[rr * 72 + ld_c] = pk;
        }
        #pragma unroll
        for (int u = 0; u < 4; u++) {
            int rr = ld_r + u * 32;
            uint4 pk = *(const uint4*)&BT[(size_t)(n0 + rr) * K + k0 + ld_c];
            *(uint4*)&Bs[rr * 72 + ld_c] = pk;
        }
        __syncthreads();

        #pragma unroll
        for (int kk = 0; kk < 64; kk += 16) {
            unsigned koff = (unsigned)(kk * 2);   // bytes
            unsigned af[4][4];
            #pragma unroll
            for (int i = 0; i < 4; i++)
                ldsm_x4(af[i][0], af[i][1], af[i][2], af[i][3], a_base[i] + koff);
            unsigned bf[4][2];
            #pragma unroll
            for (int jj = 0; jj < 2; jj++)
                ldsm_x4(bf[jj * 2][0], bf[jj * 2][1], bf[jj * 2 + 1][0], bf[jj * 2 + 1][1],
                        b_base[jj] + koff);
            #pragma unroll
            for (int i = 0; i < 4; i++)
                #pragma unroll
                for (int j = 0; j < 4; j++)
                    mma_f16(acc[i][j][0], acc[i][j][1], acc[i][j][2], acc[i][j][3],
                            af[i][0], af[i][1], af[i][2], af[i][3],
                            bf[j][0], bf[j][1]);
        }
        __syncthreads();
    }

    #pragma unroll
    for (int j = 0; j < 4; j++) {
        int col = n0 + wn + j * 8 + fc * 2;
        float2 bb = *(const float2*)&bias[col];
        #pragma unroll
        for (int i = 0; i < 4; i++) {
            int row = m0 + wm + i * 16 + fr;
            if (row < M) {
                float2 o0 = make_float2(acc[i][j][0] + bb.x, acc[i][j][1] + bb.y);
                if (F16_OUT) {
                    unsigned p = pack_h2(o0.x, o0.y);
                    *(unsigned*)&((__half*)Cout)[(size_t)row * Nout + col] = p;
                } else {
                    *(float2*)&((float*)Cout)[(size_t)row * Nout + col] = o0;
                }
            }
            if (row + 8 < M) {
                float2 o1 = make_float2(acc[i][j][2] + bb.x, acc[i][j][3] + bb.y);
                if (F16_OUT) {
                    unsigned p = pack_h2(o1.x, o1.y);
                    *(unsigned*)&((__half*)Cout)[(size_t)(row + 8) * Nout + col] = p;
                } else {
                    *(float2*)&((float*)Cout)[(size_t)(row + 8) * Nout + col] = o1;
                }
            }
        }
    }
}

// ---------------- dispersion output: table gather -----------------------------
__global__ void k_disp(float* __restrict__ out2, int N) {
    int idx = blockIdx.x * blockDim.x + threadIdx.x;
    if (idx >= N * (OUTD / 4)) return;
    int i = idx >> 7;
    int o = idx & 127;
    ((float4*)out2)[idx] = ((const float4*)d_spT)[d_ct[i] * 128 + o];
}

// ---------------- launch ------------------------------------------------------
extern "C" void kernel_launch(void* const* d_in, const int* in_sizes, int n_in,
                              void* d_out, int out_size) {
    const float* onehot  = (const float*)d_in[0];
    const float* lds     = (const float*)d_in[1];
    const int*   ei      = (const int*)  d_in[2];
    const float* W_embed = (const float*)d_in[3];
    const float* b_embed = (const float*)d_in[4];
    const float* W_l     = (const float*)d_in[5];
    const float* b_l     = (const float*)d_in[6];
    const float* W_r     = (const float*)d_in[7];
    const float* b_r     = (const float*)d_in[8];
    const float* att     = (const float*)d_in[9];
    const float* gbias   = (const float*)d_in[10];
    const float* W_out   = (const float*)d_in[11];
    const float* b_out   = (const float*)d_in[12];
    const float* disper  = (const float*)d_in[13];

    int N = in_sizes[1];
    int E = in_sizes[2] / 2;
    int scan_smem = (N + 1) * (int)sizeof(int);

    static bool inited = false;
    static cudaStream_t s1, s2;
    static cudaEvent_t evRoot, evPrep, evCSR, evDisp;
    if (!inited) {
        cudaStreamCreateWithFlags(&s1, cudaStreamNonBlocking);
        cudaStreamCreateWithFlags(&s2, cudaStreamNonBlocking);
        cudaEventCreateWithFlags(&evRoot, cudaEventDisableTiming);
        cudaEventCreateWithFlags(&evPrep, cudaEventDisableTiming);
        cudaEventCreateWithFlags(&evCSR,  cudaEventDisableTiming);
        cudaEventCreateWithFlags(&evDisp, cudaEventDisableTiming);
        cudaFuncSetAttribute(k_scan, cudaFuncAttributeMaxDynamicSharedMemorySize,
                             (NMAX + 1) * (int)sizeof(int));
        inited = true;
    }

    void *p_xlr, *p_h;
    __half *p_WlrT, *p_WoutT;
    float *p_blr;
    cudaGetSymbolAddress(&p_xlr, d_x_lr);
    cudaGetSymbolAddress(&p_h,   d_h);
    cudaGetSymbolAddress((void**)&p_WlrT,  d_WlrT);
    cudaGetSymbolAddress((void**)&p_WoutT, d_WoutT);
    cudaGetSymbolAddress((void**)&p_blr,   d_blr);

    float* out_logits = (float*)d_out;
    float* out_disp   = (float*)d_out + (size_t)N * OUTD;

    cudaEventRecord(evRoot, 0);
    cudaStreamWaitEvent(s1, evRoot, 0);

    // launches 1-2: main prep
    k_ct<<<(N + 255) / 256, 256>>>(onehot, N);
    k_asm<<<(2 * HIDDEN * EMBED + 255) / 256, 256>>>(W_l, b_l, W_r, b_r, W_out, disper);
    cudaEventRecord(evPrep, 0);

    // launch 3: CSR zero on s1
    k_zero<<<(N + 255) / 256, 256, 0, s1>>>(N);

    // launch 4 (ncu-profiled slot): fused embedding + dual transform GEMM
    k_gemm_h<true, true><<<dim3((N + 127) / 128, (2 * HIDDEN) / 128), 256>>>(
        N, EMBED, 2 * HIDDEN, nullptr, p_WlrT, p_blr, p_xlr, W_embed, b_embed, lds);

    // launches 5-7: rest of CSR build on s1
    k_hist<<<(E + 255) / 256, 256, 0, s1>>>(ei, E);
    k_scan<<<1, 1024, scan_smem, s1>>>(N);
    k_scatter<<<(E + 255) / 256, 256, 0, s1>>>(ei, E);
    cudaEventRecord(evCSR, s1);

    // launch 8: dispersion output on s2
    cudaStreamWaitEvent(s2, evPrep, 0);
    k_disp<<<(N * (OUTD / 4) + 255) / 256, 256, 0, s2>>>(out_disp, N);
    cudaEventRecord(evDisp, s2);

    // launch 9: fused edge phase (after CSR join)
    cudaStreamWaitEvent(0, evCSR, 0);
    k_edge<<<(N * 32 + 255) / 256, 256>>>(att, gbias, N);

    // launch 10: output head
    k_gemm_h<false, false><<<dim3((N + 127) / 128, OUTD / 128), 256>>>(
        N, HIDDEN, OUTD, (const __half*)p_h, p_WoutT, b_out, out_logits,
        nullptr, nullptr, nullptr);

    cudaStreamWaitEvent(0, evDisp, 0);
}

// round 14
// speedup vs baseline: 1.6158x; 1.0168x over previous
#include <cuda_runtime.h>
#include <cuda_fp16.h>
#include <math.h>

#define NMAX   50000
#define EMAX   800000
#define EMBED  256
#define HIDDEN 128
#define OUTD   512
#define NCT    32

// GEMM smem buffer geometry
#define SHALF  (128 * 72)            // halves per tile buffer
#define SBYTES (SHALF * 2)           // 18432 B
#define GEMM_SMEM (4 * SBYTES)       // As0,As1,Bs0,Bs1 = 73728 B

// ---------------- scratch (static device globals; no allocation) ------------
__device__ __half d_x_lr[(size_t)NMAX * 2 * HIDDEN];  // x_l | x_r per row, fp16
__device__ __half d_h[(size_t)NMAX * HIDDEN];         // fp16
__device__ int   d_ct[NMAX];
__device__ int   d_count[NMAX];
__device__ int   d_offs[NMAX + 1];
__device__ int   d_cursor[NMAX];
__device__ int   d_srcs[EMAX];                        // src node ids in dst-CSR order
__device__ __half d_WlrT[2 * HIDDEN * EMBED];         // [n=256][k=256] fp16 (W_l|W_r)^T
__device__ __half d_WoutT[OUTD * HIDDEN];             // [n=512][k=128] fp16 W_out^T
__device__ float d_blr[2 * HIDDEN];
__device__ float d_spT[NCT * OUTD];

// ---------------- helpers ----------------------------------------------------
__device__ __forceinline__ float eluf(float x)   { return x > 0.f ? x : __expf(x) - 1.f; }
__device__ __forceinline__ float lreluf(float x) { return x > 0.f ? x : 0.2f * x; }
__device__ __forceinline__ float softplusf(float x) {
    return fmaxf(x, 0.f) + log1pf(expf(-fabsf(x)));
}
__device__ __forceinline__ void mma_f16(float& c0, float& c1, float& c2, float& c3,
                                        unsigned a0, unsigned a1, unsigned a2, unsigned a3,
                                        unsigned b0, unsigned b1) {
    asm("mma.sync.aligned.m16n8k16.row.col.f32.f16.f16.f32 "
        "{%0,%1,%2,%3},{%4,%5,%6,%7},{%8,%9},{%0,%1,%2,%3};"
        : "+f"(c0), "+f"(c1), "+f"(c2), "+f"(c3)
        : "r"(a0), "r"(a1), "r"(a2), "r"(a3), "r"(b0), "r"(b1));
}
__device__ __forceinline__ void ldsm_x4(unsigned& r0, unsigned& r1,
                                        unsigned& r2, unsigned& r3, unsigned addr) {
    asm volatile("ldmatrix.sync.aligned.m8n8.x4.shared.b16 {%0,%1,%2,%3}, [%4];"
                 : "=r"(r0), "=r"(r1), "=r"(r2), "=r"(r3) : "r"(addr));
}
__device__ __forceinline__ unsigned smem_u32(const void* p) {
    return (unsigned)__cvta_generic_to_shared(p);
}
__device__ __forceinline__ void cp_async16(unsigned dst, const void* src) {
    asm volatile("cp.async.cg.shared.global [%0], [%1], 16;" :: "r"(dst), "l"(src));
}
__device__ __forceinline__ void cp_commit() {
    asm volatile("cp.async.commit_group;");
}
__device__ __forceinline__ void cp_wait0() {
    asm volatile("cp.async.wait_group 0;");
}
__device__ __forceinline__ void sts128(unsigned addr, uint4 v) {
    asm volatile("st.shared.v4.b32 [%0], {%1,%2,%3,%4};"
                 :: "r"(addr), "r"(v.x), "r"(v.y), "r"(v.z), "r"(v.w));
}
__device__ __forceinline__ float4 h4_to_f4(uint2 u) {
    __half2 a = *(__half2*)&u.x;
    __half2 b = *(__half2*)&u.y;
    float2 fa = __half22float2(a);
    float2 fb = __half22float2(b);
    return make_float4(fa.x, fa.y, fb.x, fb.y);
}
__device__ __forceinline__ unsigned pack_h2(float lo, float hi) {
    __half2 h = __floats2half2_rn(lo, hi);
    return *(unsigned*)&h;
}

// ---------------- tiny prep kernels -----------------------------------------
__global__ void k_ct(const float* __restrict__ onehot, int N) {
    int i = blockIdx.x * blockDim.x + threadIdx.x;
    if (i >= N) return;
    float best = -1e30f; int bi = 0;
    #pragma unroll
    for (int j = 0; j < NCT; j++) {
        float v = onehot[(size_t)i * NCT + j];
        if (v > best) { best = v; bi = j; }
    }
    d_ct[i] = bi;
}

__global__ void k_zero(int N) {
    int i = blockIdx.x * blockDim.x + threadIdx.x;
    if (i < N) d_count[i] = 0;
}

__global__ void k_asm(const float* __restrict__ W_l, const float* __restrict__ b_l,
                      const float* __restrict__ W_r, const float* __restrict__ b_r,
                      const float* __restrict__ W_out, const float* __restrict__ dispersion) {
    int idx = blockIdx.x * blockDim.x + threadIdx.x;
    if (idx < 2 * HIDDEN * EMBED) {          // WlrT [j=256][k=256]
        int j = idx >> 8;
        int k = idx & 255;
        float v = (j < HIDDEN) ? W_l[k * HIDDEN + j] : W_r[k * HIDDEN + (j - HIDDEN)];
        d_WlrT[idx] = __float2half(v);
    }
    if (idx < OUTD * HIDDEN) {               // WoutT [j=512][k=128]
        int j = idx >> 7;
        int k = idx & 127;
        d_WoutT[idx] = __float2half(W_out[k * OUTD + j]);
    }
    if (idx < 2 * HIDDEN)
        d_blr[idx] = (idx < HIDDEN) ? b_l[idx] : b_r[idx - HIDDEN];
    if (idx < NCT * OUTD) {
        int ct = idx / OUTD, o = idx % OUTD;
        d_spT[idx] = softplusf(dispersion[o * NCT + ct]);
    }
}

// ---------------- CSR build --------------------------------------------------
__global__ void k_hist(const int* __restrict__ ei, int E) {
    int e = blockIdx.x * blockDim.x + threadIdx.x;
    if (e >= E) return;
    atomicAdd(&d_count[ei[E + e]], 1);
}

__global__ void k_scan(int N) {
    extern __shared__ int sc[];
    __shared__ int part[1024];
    int t = threadIdx.x;
    for (int i = t; i < N; i += 1024) sc[i] = d_count[i];
    __syncthreads();
    int chunk = (N + 1023) / 1024;
    int b = t * chunk;
    int e = min(b + chunk, N);
    int s = 0;
    for (int i = b; i < e; i++) s += sc[i];
    part[t] = s;
    __syncthreads();
    for (int d = 1; d < 1024; d <<= 1) {
        int v = (t >= d) ? part[t - d] : 0;
        __syncthreads();
        part[t] += v;
        __syncthreads();
    }
    int run = (t == 0) ? 0 : part[t - 1];
    for (int i = b; i < e; i++) {
        int c = sc[i];
        sc[i] = run;
        run += c;
    }
    __syncthreads();
    for (int i = t; i < N; i += 1024) {
        int v = sc[i];
        d_offs[i] = v;
        d_cursor[i] = v;
    }
    if (t == 1023) d_offs[N] = run;
}

__global__ void k_scatter(const int* __restrict__ ei, int E) {
    int e = blockIdx.x * blockDim.x + threadIdx.x;
    if (e >= E) return;
    int s = ei[e];
    int d = ei[E + e];
    int pos = atomicAdd(&d_cursor[d], 1);
    d_srcs[pos] = s;
}

// ---------------- fused edge phase (proven form, fp16 in/out) ------------------
__global__ void k_edge(const float* __restrict__ att, const float* __restrict__ gat_bias,
                       int N) {
    int warp = (blockIdx.x * blockDim.x + threadIdx.x) >> 5;
    int lane = threadIdx.x & 31;
    if (warp >= N) return;
    int start = d_offs[warp];
    int end   = d_offs[warp + 1];

    const uint2* x2 = (const uint2*)d_x_lr;
    float4 xr = h4_to_f4(x2[(size_t)warp * 64 + 32 + lane]);
    float4 a  = ((const float4*)att)[lane];

    float4 acc = make_float4(0.f, 0.f, 0.f, 0.f);
    float denom = 0.f;

    if (start < end) {
        uint2 raw = x2[(size_t)d_srcs[start] * 64 + lane];
        for (int i = start; i < end; i++) {
            uint2 rawn;
            if (i + 1 < end)
                rawn = x2[(size_t)d_srcs[i + 1] * 64 + lane];
            float4 xl = h4_to_f4(raw);
            float p = lreluf(xl.x + xr.x) * a.x
                    + lreluf(xl.y + xr.y) * a.y
                    + lreluf(xl.z + xr.z) * a.z
                    + lreluf(xl.w + xr.w) * a.w;
            #pragma unroll
            for (int o = 16; o; o >>= 1) p += __shfl_xor_sync(0xffffffffu, p, o);
            float al = __expf(p);
            acc.x = fmaf(al, xl.x, acc.x);
            acc.y = fmaf(al, xl.y, acc.y);
            acc.z = fmaf(al, xl.z, acc.z);
            acc.w = fmaf(al, xl.w, acc.w);
            denom += al;
            raw = rawn;
        }
    }
    float inv = 1.f / (denom + 1e-16f);
    float4 gb = ((const float4*)gat_bias)[lane];
    uint2 st;
    st.x = pack_h2(eluf(fmaf(acc.x, inv, gb.x)), eluf(fmaf(acc.y, inv, gb.y)));
    st.y = pack_h2(eluf(fmaf(acc.z, inv, gb.z)), eluf(fmaf(acc.w, inv, gb.w)));
    ((uint2*)d_h)[(size_t)warp * 32 + lane] = st;
}

// ---------------- fp16 HMMA GEMM, KT=64, double-buffered smem + cp.async ------
// 128x128 block tile, 8 warps 2(m)x4(n), warp tile 64x32, m16n8k16 4x4 frags.
// Dynamic smem: As0 | As1 | Bs0 | Bs1, each 128x72 halves. One sync per chunk.
template<bool FUSE_EMB, bool F16_OUT>
__global__ __launch_bounds__(256, 2) void k_gemm_h(
    int M, int K, int Nout,
    const __half* __restrict__ A, const __half* __restrict__ BT,
    const float* __restrict__ bias, void* __restrict__ Cout,
    const float* __restrict__ W_embed, const float* __restrict__ b_embed,
    const float* __restrict__ lds)
{
    extern __shared__ __half sm[];
    __half* As = sm;                 // two buffers, SBYTES apart
    __half* Bs = sm + 2 * SHALF;
    int tid  = threadIdx.x;
    int lane = tid & 31;
    int wid  = tid >> 5;
    int wm   = (wid >> 2) * 64;
    int wn   = (wid & 3) * 32;
    int m0 = blockIdx.x * 128;
    int n0 = blockIdx.y * 128;

    float acc[4][4][4];
    #pragma unroll
    for (int i = 0; i < 4; i++)
        #pragma unroll
        for (int j = 0; j < 4; j++)
            #pragma unroll
            for (int r = 0; r < 4; r++) acc[i][j][r] = 0.f;

    int ld_r = tid >> 3;          // 0..31 (4 rows per thread, step 32)
    int ld_c = (tid & 7) * 8;     // 8 halves per load, covers 64

    int fr = lane >> 2;
    int fc = lane & 3;

    // per-thread store addresses (buf0)
    unsigned a_st[4], b_st[4];
    #pragma unroll
    for (int u = 0; u < 4; u++) {
        a_st[u] = smem_u32(&As[(ld_r + u * 32) * 72 + ld_c]);
        b_st[u] = smem_u32(&Bs[(ld_r + u * 32) * 72 + ld_c]);
    }

    // ldmatrix lane-address bases (buf0)
    int lrow = lane & 7;
    int g    = lane >> 3;
    unsigned a_rd[4], b_rd[2];
    #pragma unroll
    for (int i = 0; i < 4; i++)
        a_rd[i] = smem_u32(&As[(wm + i * 16 + (g & 1) * 8 + lrow) * 72 + (g >> 1) * 8]);
    #pragma unroll
    for (int jj = 0; jj < 2; jj++)
        b_rd[jj] = smem_u32(&Bs[(wn + jj * 16 + (g >> 1) * 8 + lrow) * 72 + (g & 1) * 8]);

    // hoisted per-row gather state for fused embedding loader
    int   ctv[4];
    float lv[4];
    bool  okv[4];
    if (FUSE_EMB) {
        #pragma unroll
        for (int u = 0; u < 4; u++) {
            int row = m0 + ld_r + u * 32;
            okv[u] = (row < M);
            ctv[u] = okv[u] ? d_ct[row] : 0;
            lv[u]  = okv[u] ? lds[row] : 0.f;
        }
    }

    auto load_tile = [&](int k0, int buf) {
        unsigned off = buf ? (unsigned)SBYTES : 0u;
        // B via cp.async (rows always valid: Nout multiple of 128)
        #pragma unroll
        for (int u = 0; u < 4; u++) {
            int rr = ld_r + u * 32;
            cp_async16(b_st[u] + off, &BT[(size_t)(n0 + rr) * K + k0 + ld_c]);
        }
        cp_commit();
        // A: fused-embedding math -> STS, or cp.async for plain path
        #pragma unroll
        for (int u = 0; u < 4; u++) {
            if (FUSE_EMB) {
                uint4 pk = make_uint4(0, 0, 0, 0);
                if (okv[u]) {
                    int ct = ctv[u];
                    float l = lv[u];
                    int kk = k0 + ld_c;
                    float4 we0 = *(const float4*)&W_embed[ct * EMBED + kk];
                    float4 we1 = *(const float4*)&W_embed[ct * EMBED + kk + 4];
                    float4 wl0 = *(const float4*)&W_embed[NCT * EMBED + kk];
                    float4 wl1 = *(const float4*)&W_embed[NCT * EMBED + kk + 4];
                    float4 be0 = *(const float4*)&b_embed[kk];
                    float4 be1 = *(const float4*)&b_embed[kk + 4];
                    pk.x = pack_h2(eluf(fmaf(l, wl0.x, we0.x) + be0.x),
                                   eluf(fmaf(l, wl0.y, we0.y) + be0.y));
                    pk.y = pack_h2(eluf(fmaf(l, wl0.z, we0.z) + be0.z),
                                   eluf(fmaf(l, wl0.w, we0.w) + be0.w));
                    pk.z = pack_h2(eluf(fmaf(l, wl1.x, we1.x) + be1.x),
                                   eluf(fmaf(l, wl1.y, we1.y) + be1.y));
                    pk.w = pack_h2(eluf(fmaf(l, wl1.z, we1.z) + be1.z),
                                   eluf(fmaf(l, wl1.w, we1.w) + be1.w));
                }
                sts128(a_st[u] + off, pk);
            } else {
                int row = m0 + ld_r + u * 32;
                if (row < M)
                    cp_async16(a_st[u] + off, &A[(size_t)row * K + k0 + ld_c]);
                else
                    sts128(a_st[u] + off, make_uint4(0, 0, 0, 0));
            }
        }
        if (!FUSE_EMB) cp_commit();
    };

    int nch = K >> 6;   // KT = 64
    load_tile(0, 0);
    cp_wait0();
    __syncthreads();

    int buf = 0;
    for (int c = 0; c < nch; c++) {
        if (c + 1 < nch) load_tile((c + 1) << 6, buf ^ 1);

        unsigned roff = buf ? (unsigned)SBYTES : 0u;
        #pragma unroll
        for (int kk = 0; kk < 64; kk += 16) {
            unsigned koff = roff + (unsigned)(kk * 2);
            unsigned af[4][4];
            #pragma unroll
            for (int i = 0; i < 4; i++)
                ldsm_x4(af[i][0], af[i][1], af[i][2], af[i][3], a_rd[i] + koff);
            unsigned bf[4][2];
            #pragma unroll
            for (int jj = 0; jj < 2; jj++)
                ldsm_x4(bf[jj * 2][0], bf[jj * 2][1], bf[jj * 2 + 1][0], bf[jj * 2 + 1][1],
                        b_rd[jj] + koff);
            #pragma unroll
            for (int i = 0; i < 4; i++)
                #pragma unroll
                for (int j = 0; j < 4; j++)
                    mma_f16(acc[i][j][0], acc[i][j][1], acc[i][j][2], acc[i][j][3],
                            af[i][0], af[i][1], af[i][2], af[i][3],
                            bf[j][0], bf[j][1]);
        }

        if (c + 1 < nch) {
            cp_wait0();
            __syncthreads();
        }
        buf ^= 1;
    }

    #pragma unroll
    for (int j = 0; j < 4; j++) {
        int col = n0 + wn + j * 8 + fc * 2;
        float2 bb = *(const float2*)&bias[col];
        #pragma unroll
        for (int i = 0; i < 4; i++) {
            int row = m0 + wm + i * 16 + fr;
            if (row < M) {
                float2 o0 = make_float2(acc[i][j][0] + bb.x, acc[i][j][1] + bb.y);
                if (F16_OUT) {
                    unsigned p = pack_h2(o0.x, o0.y);
                    *(unsigned*)&((__half*)Cout)[(size_t)row * Nout + col] = p;
                } else {
                    *(float2*)&((float*)Cout)[(size_t)row * Nout + col] = o0;
                }
            }
            if (row + 8 < M) {
                float2 o1 = make_float2(acc[i][j][2] + bb.x, acc[i][j][3] + bb.y);
                if (F16_OUT) {
                    unsigned p = pack_h2(o1.x, o1.y);
                    *(unsigned*)&((__half*)Cout)[(size_t)(row + 8) * Nout + col] = p;
                } else {
                    *(float2*)&((float*)Cout)[(size_t)(row + 8) * Nout + col] = o1;
                }
            }
        }
    }
}

// ---------------- dispersion output: table gather -----------------------------
__global__ void k_disp(float* __restrict__ out2, int N) {
    int idx = blockIdx.x * blockDim.x + threadIdx.x;
    if (idx >= N * (OUTD / 4)) return;
    int i = idx >> 7;
    int o = idx & 127;
    ((float4*)out2)[idx] = ((const float4*)d_spT)[d_ct[i] * 128 + o];
}

// ---------------- launch ------------------------------------------------------
extern "C" void kernel_launch(void* const* d_in, const int* in_sizes, int n_in,
                              void* d_out, int out_size) {
    const float* onehot  = (const float*)d_in[0];
    const float* lds     = (const float*)d_in[1];
    const int*   ei      = (const int*)  d_in[2];
    const float* W_embed = (const float*)d_in[3];
    const float* b_embed = (const float*)d_in[4];
    const float* W_l     = (const float*)d_in[5];
    const float* b_l     = (const float*)d_in[6];
    const float* W_r     = (const float*)d_in[7];
    const float* b_r     = (const float*)d_in[8];
    const float* att     = (const float*)d_in[9];
    const float* gbias   = (const float*)d_in[10];
    const float* W_out   = (const float*)d_in[11];
    const float* b_out   = (const float*)d_in[12];
    const float* disper  = (const float*)d_in[13];

    int N = in_sizes[1];
    int E = in_sizes[2] / 2;
    int scan_smem = (N + 1) * (int)sizeof(int);

    static bool inited = false;
    static cudaStream_t s1, s2;
    static cudaEvent_t evRoot, evPrep, evCSR, evDisp;
    if (!inited) {
        cudaStreamCreateWithFlags(&s1, cudaStreamNonBlocking);
        cudaStreamCreateWithFlags(&s2, cudaStreamNonBlocking);
        cudaEventCreateWithFlags(&evRoot, cudaEventDisableTiming);
        cudaEventCreateWithFlags(&evPrep, cudaEventDisableTiming);
        cudaEventCreateWithFlags(&evCSR,  cudaEventDisableTiming);
        cudaEventCreateWithFlags(&evDisp, cudaEventDisableTiming);
        cudaFuncSetAttribute(k_scan, cudaFuncAttributeMaxDynamicSharedMemorySize,
                             (NMAX + 1) * (int)sizeof(int));
        cudaFuncSetAttribute(k_gemm_h<true, true>,
                             cudaFuncAttributeMaxDynamicSharedMemorySize, GEMM_SMEM);
        cudaFuncSetAttribute(k_gemm_h<false, false>,
                             cudaFuncAttributeMaxDynamicSharedMemorySize, GEMM_SMEM);
        inited = true;
    }

    void *p_xlr, *p_h;
    __half *p_WlrT, *p_WoutT;
    float *p_blr;
    cudaGetSymbolAddress(&p_xlr, d_x_lr);
    cudaGetSymbolAddress(&p_h,   d_h);
    cudaGetSymbolAddress((void**)&p_WlrT,  d_WlrT);
    cudaGetSymbolAddress((void**)&p_WoutT, d_WoutT);
    cudaGetSymbolAddress((void**)&p_blr,   d_blr);

    float* out_logits = (float*)d_out;
    float* out_disp   = (float*)d_out + (size_t)N * OUTD;

    cudaEventRecord(evRoot, 0);
    cudaStreamWaitEvent(s1, evRoot, 0);

    // launches 1-2: main prep
    k_ct<<<(N + 255) / 256, 256>>>(onehot, N);
    k_asm<<<(2 * HIDDEN * EMBED + 255) / 256, 256>>>(W_l, b_l, W_r, b_r, W_out, disper);
    cudaEventRecord(evPrep, 0);

    // launch 3: CSR zero on s1
    k_zero<<<(N + 255) / 256, 256, 0, s1>>>(N);

    // launch 4 (ncu-profiled slot): fused embedding + dual transform GEMM
    k_gemm_h<true, true><<<dim3((N + 127) / 128, (2 * HIDDEN) / 128), 256, GEMM_SMEM>>>(
        N, EMBED, 2 * HIDDEN, nullptr, p_WlrT, p_blr, p_xlr, W_embed, b_embed, lds);

    // launches 5-7: rest of CSR build on s1
    k_hist<<<(E + 255) / 256, 256, 0, s1>>>(ei, E);
    k_scan<<<1, 1024, scan_smem, s1>>>(N);
    k_scatter<<<(E + 255) / 256, 256, 0, s1>>>(ei, E);
    cudaEventRecord(evCSR, s1);

    // launch 8: dispersion output on s2
    cudaStreamWaitEvent(s2, evPrep, 0);
    k_disp<<<(N * (OUTD / 4) + 255) / 256, 256, 0, s2>>>(out_disp, N);
    cudaEventRecord(evDisp, s2);

    // launch 9: fused edge phase (after CSR join)
    cudaStreamWaitEvent(0, evCSR, 0);
    k_edge<<<(N * 32 + 255) / 256, 256>>>(att, gbias, N);

    // launch 10: output head
    k_gemm_h<false, false><<<dim3((N + 127) / 128, OUTD / 128), 256, GEMM_SMEM>>>(
        N, HIDDEN, OUTD, (const __half*)p_h, p_WoutT, b_out, out_logits,
        nullptr, nullptr, nullptr);

    cudaStreamWaitEvent(0, evDisp, 0);
}

// round 16
// speedup vs baseline: 1.6455x; 1.0183x over previous
#include <cuda_runtime.h>
#include <cuda_fp16.h>
#include <math.h>

#define NMAX   50000
#define EMAX   800000
#define EMBED  256
#define HIDDEN 128
#define OUTD   512
#define NCT    32

// GEMM smem buffer geometry
#define SHALF  (128 * 72)            // halves per tile buffer
#define SBYTES (SHALF * 2)           // 18432 B
#define GEMM_SMEM (4 * SBYTES)       // As0,As1,Bs0,Bs1 = 73728 B

// ---------------- scratch (static device globals; no allocation) ------------
__device__ __half d_x_lr[(size_t)NMAX * 2 * HIDDEN];  // x_l | x_r per row, fp16
__device__ __half d_h[(size_t)NMAX * HIDDEN];         // fp16
__device__ int   d_ct[NMAX];
__device__ int   d_count[NMAX];
__device__ int   d_offs[NMAX + 1];
__device__ int   d_cursor[NMAX];
__device__ int   d_srcs[EMAX];                        // src node ids in dst-CSR order
__device__ __half d_WlrT[2 * HIDDEN * EMBED];         // [n=256][k=256] fp16 (W_l|W_r)^T
__device__ __half d_WoutT[OUTD * HIDDEN];             // [n=512][k=128] fp16 W_out^T
__device__ float d_blr[2 * HIDDEN];
__device__ float d_spT[NCT * OUTD];

// ---------------- helpers ----------------------------------------------------
__device__ __forceinline__ float eluf(float x)   { return x > 0.f ? x : __expf(x) - 1.f; }
__device__ __forceinline__ float softplusf(float x) {
    return fmaxf(x, 0.f) + log1pf(expf(-fabsf(x)));
}
__device__ __forceinline__ void mma_f16(float& c0, float& c1, float& c2, float& c3,
                                        unsigned a0, unsigned a1, unsigned a2, unsigned a3,
                                        unsigned b0, unsigned b1) {
    asm("mma.sync.aligned.m16n8k16.row.col.f32.f16.f16.f32 "
        "{%0,%1,%2,%3},{%4,%5,%6,%7},{%8,%9},{%0,%1,%2,%3};"
        : "+f"(c0), "+f"(c1), "+f"(c2), "+f"(c3)
        : "r"(a0), "r"(a1), "r"(a2), "r"(a3), "r"(b0), "r"(b1));
}
__device__ __forceinline__ void ldsm_x4(unsigned& r0, unsigned& r1,
                                        unsigned& r2, unsigned& r3, unsigned addr) {
    asm volatile("ldmatrix.sync.aligned.m8n8.x4.shared.b16 {%0,%1,%2,%3}, [%4];"
                 : "=r"(r0), "=r"(r1), "=r"(r2), "=r"(r3) : "r"(addr));
}
__device__ __forceinline__ unsigned smem_u32(const void* p) {
    return (unsigned)__cvta_generic_to_shared(p);
}
__device__ __forceinline__ void cp_async16(unsigned dst, const void* src) {
    asm volatile("cp.async.cg.shared.global [%0], [%1], 16;" :: "r"(dst), "l"(src));
}
__device__ __forceinline__ void cp_commit() {
    asm volatile("cp.async.commit_group;");
}
__device__ __forceinline__ void cp_wait0() {
    asm volatile("cp.async.wait_group 0;");
}
__device__ __forceinline__ void sts128(unsigned addr, uint4 v) {
    asm volatile("st.shared.v4.b32 [%0], {%1,%2,%3,%4};"
                 :: "r"(addr), "r"(v.x), "r"(v.y), "r"(v.z), "r"(v.w));
}
__device__ __forceinline__ float4 h4_to_f4(uint2 u) {
    __half2 a = *(__half2*)&u.x;
    __half2 b = *(__half2*)&u.y;
    float2 fa = __half22float2(a);
    float2 fb = __half22float2(b);
    return make_float4(fa.x, fa.y, fb.x, fb.y);
}
__device__ __forceinline__ unsigned pack_h2(float lo, float hi) {
    __half2 h = __floats2half2_rn(lo, hi);
    return *(unsigned*)&h;
}

// ---------------- tiny prep kernels -----------------------------------------
__global__ void k_ct(const float* __restrict__ onehot, int N) {
    int i = blockIdx.x * blockDim.x + threadIdx.x;
    if (i >= N) return;
    float best = -1e30f; int bi = 0;
    #pragma unroll
    for (int j = 0; j < NCT; j++) {
        float v = onehot[(size_t)i * NCT + j];
        if (v > best) { best = v; bi = j; }
    }
    d_ct[i] = bi;
}

__global__ void k_zero(int N) {
    int i = blockIdx.x * blockDim.x + threadIdx.x;
    if (i < N) d_count[i] = 0;
}

__global__ void k_asm(const float* __restrict__ W_l, const float* __restrict__ b_l,
                      const float* __restrict__ W_r, const float* __restrict__ b_r,
                      const float* __restrict__ W_out, const float* __restrict__ dispersion) {
    int idx = blockIdx.x * blockDim.x + threadIdx.x;
    if (idx < 2 * HIDDEN * EMBED) {          // WlrT [j=256][k=256]
        int j = idx >> 8;
        int k = idx & 255;
        float v = (j < HIDDEN) ? W_l[k * HIDDEN + j] : W_r[k * HIDDEN + (j - HIDDEN)];
        d_WlrT[idx] = __float2half(v);
    }
    if (idx < OUTD * HIDDEN) {               // WoutT [j=512][k=128]
        int j = idx >> 7;
        int k = idx & 127;
        d_WoutT[idx] = __float2half(W_out[k * OUTD + j]);
    }
    if (idx < 2 * HIDDEN)
        d_blr[idx] = (idx < HIDDEN) ? b_l[idx] : b_r[idx - HIDDEN];
    if (idx < NCT * OUTD) {
        int ct = idx / OUTD, o = idx % OUTD;
        d_spT[idx] = softplusf(dispersion[o * NCT + ct]);
    }
}

// ---------------- CSR build --------------------------------------------------
__global__ void k_hist(const int* __restrict__ ei, int E) {
    int e = blockIdx.x * blockDim.x + threadIdx.x;
    if (e >= E) return;
    atomicAdd(&d_count[ei[E + e]], 1);
}

__global__ void k_scan(int N) {
    extern __shared__ int sc[];
    __shared__ int part[1024];
    int t = threadIdx.x;
    for (int i = t; i < N; i += 1024) sc[i] = d_count[i];
    __syncthreads();
    int chunk = (N + 1023) / 1024;
    int b = t * chunk;
    int e = min(b + chunk, N);
    int s = 0;
    for (int i = b; i < e; i++) s += sc[i];
    part[t] = s;
    __syncthreads();
    for (int d = 1; d < 1024; d <<= 1) {
        int v = (t >= d) ? part[t - d] : 0;
        __syncthreads();
        part[t] += v;
        __syncthreads();
    }
    int run = (t == 0) ? 0 : part[t - 1];
    for (int i = b; i < e; i++) {
        int c = sc[i];
        sc[i] = run;
        run += c;
    }
    __syncthreads();
    for (int i = t; i < N; i += 1024) {
        int v = sc[i];
        d_offs[i] = v;
        d_cursor[i] = v;
    }
    if (t == 1023) d_offs[N] = run;
}

__global__ void k_scatter(const int* __restrict__ ei, int E) {
    int e = blockIdx.x * blockDim.x + threadIdx.x;
    if (e >= E) return;
    int s = ei[e];
    int d = ei[E + e];
    int pos = atomicAdd(&d_cursor[d], 1);
    d_srcs[pos] = s;
}

// ---------------- fused edge phase: warp per dst, half2 dot + shfl reduce -----
// leaky_relu(x, 0.2) == max(x, 0.2*x); dot computed in half2 (2x fewer ops),
// logit reduced across lanes in fp32; aggregation accumulates in fp32.
__global__ void k_edge(const float* __restrict__ att, const float* __restrict__ gat_bias,
                       int N) {
    int warp = (blockIdx.x * blockDim.x + threadIdx.x) >> 5;
    int lane = threadIdx.x & 31;
    if (warp >= N) return;
    int start = d_offs[warp];
    int end   = d_offs[warp + 1];

    const uint2* x2 = (const uint2*)d_x_lr;   // row = 64 uint2 (32 x_l + 32 x_r)
    uint2 xru = x2[(size_t)warp * 64 + 32 + lane];
    __half2 xr0 = *(__half2*)&xru.x;
    __half2 xr1 = *(__half2*)&xru.y;
    float4 af = ((const float4*)att)[lane];
    __half2 a0 = __floats2half2_rn(af.x, af.y);
    __half2 a1 = __floats2half2_rn(af.z, af.w);
    const __half2 slope = __float2half2_rn(0.2f);

    float4 acc = make_float4(0.f, 0.f, 0.f, 0.f);
    float denom = 0.f;

    if (start < end) {
        uint2 raw = x2[(size_t)d_srcs[start] * 64 + lane];
        for (int i = start; i < end; i++) {
            uint2 rawn;
            if (i + 1 < end)
                rawn = x2[(size_t)d_srcs[i + 1] * 64 + lane];
            __half2 xl0 = *(__half2*)&raw.x;
            __half2 xl1 = *(__half2*)&raw.y;
            __half2 s0 = __hadd2(xl0, xr0);
            __half2 s1 = __hadd2(xl1, xr1);
            __half2 m0 = __hmax2(s0, __hmul2(s0, slope));
            __half2 m1 = __hmax2(s1, __hmul2(s1, slope));
            __half2 p2 = __hfma2(m0, a0, __hmul2(m1, a1));
            float2 pf = __half22float2(p2);
            float p = pf.x + pf.y;
            #pragma unroll
            for (int o = 16; o; o >>= 1) p += __shfl_xor_sync(0xffffffffu, p, o);
            float al = __expf(p);
            float4 xl = h4_to_f4(raw);
            acc.x = fmaf(al, xl.x, acc.x);
            acc.y = fmaf(al, xl.y, acc.y);
            acc.z = fmaf(al, xl.z, acc.z);
            acc.w = fmaf(al, xl.w, acc.w);
            denom += al;
            raw = rawn;
        }
    }
    float inv = 1.f / (denom + 1e-16f);
    float4 gb = ((const float4*)gat_bias)[lane];
    uint2 st;
    st.x = pack_h2(eluf(fmaf(acc.x, inv, gb.x)), eluf(fmaf(acc.y, inv, gb.y)));
    st.y = pack_h2(eluf(fmaf(acc.z, inv, gb.z)), eluf(fmaf(acc.w, inv, gb.w)));
    ((uint2*)d_h)[(size_t)warp * 32 + lane] = st;
}

// ---------------- fp16 HMMA GEMM, KT=64, double-buffered smem + cp.async ------
template<bool FUSE_EMB, bool F16_OUT>
__global__ __launch_bounds__(256, 2) void k_gemm_h(
    int M, int K, int Nout,
    const __half* __restrict__ A, const __half* __restrict__ BT,
    const float* __restrict__ bias, void* __restrict__ Cout,
    const float* __restrict__ W_embed, const float* __restrict__ b_embed,
    const float* __restrict__ lds)
{
    extern __shared__ __half sm[];
    __half* As = sm;
    __half* Bs = sm + 2 * SHALF;
    int tid  = threadIdx.x;
    int lane = tid & 31;
    int wid  = tid >> 5;
    int wm   = (wid >> 2) * 64;
    int wn   = (wid & 3) * 32;
    int m0 = blockIdx.x * 128;
    int n0 = blockIdx.y * 128;

    float acc[4][4][4];
    #pragma unroll
    for (int i = 0; i < 4; i++)
        #pragma unroll
        for (int j = 0; j < 4; j++)
            #pragma unroll
            for (int r = 0; r < 4; r++) acc[i][j][r] = 0.f;

    int ld_r = tid >> 3;
    int ld_c = (tid & 7) * 8;

    int fr = lane >> 2;
    int fc = lane & 3;

    unsigned a_st[4], b_st[4];
    #pragma unroll
    for (int u = 0; u < 4; u++) {
        a_st[u] = smem_u32(&As[(ld_r + u * 32) * 72 + ld_c]);
        b_st[u] = smem_u32(&Bs[(ld_r + u * 32) * 72 + ld_c]);
    }

    int lrow = lane & 7;
    int g    = lane >> 3;
    unsigned a_rd[4], b_rd[2];
    #pragma unroll
    for (int i = 0; i < 4; i++)
        a_rd[i] = smem_u32(&As[(wm + i * 16 + (g & 1) * 8 + lrow) * 72 + (g >> 1) * 8]);
    #pragma unroll
    for (int jj = 0; jj < 2; jj++)
        b_rd[jj] = smem_u32(&Bs[(wn + jj * 16 + (g >> 1) * 8 + lrow) * 72 + (g & 1) * 8]);

    int   ctv[4];
    float lv[4];
    bool  okv[4];
    if (FUSE_EMB) {
        #pragma unroll
        for (int u = 0; u < 4; u++) {
            int row = m0 + ld_r + u * 32;
            okv[u] = (row < M);
            ctv[u] = okv[u] ? d_ct[row] : 0;
            lv[u]  = okv[u] ? lds[row] : 0.f;
        }
    }

    auto load_tile = [&](int k0, int buf) {
        unsigned off = buf ? (unsigned)SBYTES : 0u;
        #pragma unroll
        for (int u = 0; u < 4; u++) {
            int rr = ld_r + u * 32;
            cp_async16(b_st[u] + off, &BT[(size_t)(n0 + rr) * K + k0 + ld_c]);
        }
        cp_commit();
        #pragma unroll
        for (int u = 0; u < 4; u++) {
            if (FUSE_EMB) {
                uint4 pk = make_uint4(0, 0, 0, 0);
                if (okv[u]) {
                    int ct = ctv[u];
                    float l = lv[u];
                    int kk = k0 + ld_c;
                    float4 we0 = *(const float4*)&W_embed[ct * EMBED + kk];
                    float4 we1 = *(const float4*)&W_embed[ct * EMBED + kk + 4];
                    float4 wl0 = *(const float4*)&W_embed[NCT * EMBED + kk];
                    float4 wl1 = *(const float4*)&W_embed[NCT * EMBED + kk + 4];
                    float4 be0 = *(const float4*)&b_embed[kk];
                    float4 be1 = *(const float4*)&b_embed[kk + 4];
                    pk.x = pack_h2(eluf(fmaf(l, wl0.x, we0.x) + be0.x),
                                   eluf(fmaf(l, wl0.y, we0.y) + be0.y));
                    pk.y = pack_h2(eluf(fmaf(l, wl0.z, we0.z) + be0.z),
                                   eluf(fmaf(l, wl0.w, we0.w) + be0.w));
                    pk.z = pack_h2(eluf(fmaf(l, wl1.x, we1.x) + be1.x),
                                   eluf(fmaf(l, wl1.y, we1.y) + be1.y));
                    pk.w = pack_h2(eluf(fmaf(l, wl1.z, we1.z) + be1.z),
                                   eluf(fmaf(l, wl1.w, we1.w) + be1.w));
                }
                sts128(a_st[u] + off, pk);
            } else {
                int row = m0 + ld_r + u * 32;
                if (row < M)
                    cp_async16(a_st[u] + off, &A[(size_t)row * K + k0 + ld_c]);
                else
                    sts128(a_st[u] + off, make_uint4(0, 0, 0, 0));
            }
        }
        if (!FUSE_EMB) cp_commit();
    };

    int nch = K >> 6;
    load_tile(0, 0);
    cp_wait0();
    __syncthreads();

    int buf = 0;
    for (int c = 0; c < nch; c++) {
        if (c + 1 < nch) load_tile((c + 1) << 6, buf ^ 1);

        unsigned roff = buf ? (unsigned)SBYTES : 0u;
        #pragma unroll
        for (int kk = 0; kk < 64; kk += 16) {
            unsigned koff = roff + (unsigned)(kk * 2);
            unsigned af[4][4];
            #pragma unroll
            for (int i = 0; i < 4; i++)
                ldsm_x4(af[i][0], af[i][1], af[i][2], af[i][3], a_rd[i] + koff);
            unsigned bf[4][2];
            #pragma unroll
            for (int jj = 0; jj < 2; jj++)
                ldsm_x4(bf[jj * 2][0], bf[jj * 2][1], bf[jj * 2 + 1][0], bf[jj * 2 + 1][1],
                        b_rd[jj] + koff);
            #pragma unroll
            for (int i = 0; i < 4; i++)
                #pragma unroll
                for (int j = 0; j < 4; j++)
                    mma_f16(acc[i][j][0], acc[i][j][1], acc[i][j][2], acc[i][j][3],
                            af[i][0], af[i][1], af[i][2], af[i][3],
                            bf[j][0], bf[j][1]);
        }

        if (c + 1 < nch) {
            cp_wait0();
            __syncthreads();
        }
        buf ^= 1;
    }

    #pragma unroll
    for (int j = 0; j < 4; j++) {
        int col = n0 + wn + j * 8 + fc * 2;
        float2 bb = *(const float2*)&bias[col];
        #pragma unroll
        for (int i = 0; i < 4; i++) {
            int row = m0 + wm + i * 16 + fr;
            if (row < M) {
                float2 o0 = make_float2(acc[i][j][0] + bb.x, acc[i][j][1] + bb.y);
                if (F16_OUT) {
                    unsigned p = pack_h2(o0.x, o0.y);
                    *(unsigned*)&((__half*)Cout)[(size_t)row * Nout + col] = p;
                } else {
                    *(float2*)&((float*)Cout)[(size_t)row * Nout + col] = o0;
                }
            }
            if (row + 8 < M) {
                float2 o1 = make_float2(acc[i][j][2] + bb.x, acc[i][j][3] + bb.y);
                if (F16_OUT) {
                    unsigned p = pack_h2(o1.x, o1.y);
                    *(unsigned*)&((__half*)Cout)[(size_t)(row + 8) * Nout + col] = p;
                } else {
                    *(float2*)&((float*)Cout)[(size_t)(row + 8) * Nout + col] = o1;
                }
            }
        }
    }
}

// ---------------- dispersion output: table gather -----------------------------
__global__ void k_disp(float* __restrict__ out2, int N) {
    int idx = blockIdx.x * blockDim.x + threadIdx.x;
    if (idx >= N * (OUTD / 4)) return;
    int i = idx >> 7;
    int o = idx & 127;
    ((float4*)out2)[idx] = ((const float4*)d_spT)[d_ct[i] * 128 + o];
}

// ---------------- launch ------------------------------------------------------
extern "C" void kernel_launch(void* const* d_in, const int* in_sizes, int n_in,
                              void* d_out, int out_size) {
    const float* onehot  = (const float*)d_in[0];
    const float* lds     = (const float*)d_in[1];
    const int*   ei      = (const int*)  d_in[2];
    const float* W_embed = (const float*)d_in[3];
    const float* b_embed = (const float*)d_in[4];
    const float* W_l     = (const float*)d_in[5];
    const float* b_l     = (const float*)d_in[6];
    const float* W_r     = (const float*)d_in[7];
    const float* b_r     = (const float*)d_in[8];
    const float* att     = (const float*)d_in[9];
    const float* gbias   = (const float*)d_in[10];
    const float* W_out   = (const float*)d_in[11];
    const float* b_out   = (const float*)d_in[12];
    const float* disper  = (const float*)d_in[13];

    int N = in_sizes[1];
    int E = in_sizes[2] / 2;
    int scan_smem = (N + 1) * (int)sizeof(int);

    static bool inited = false;
    static cudaStream_t s1, s2;
    static cudaEvent_t evRoot, evPrep, evCSR, evDisp;
    if (!inited) {
        cudaStreamCreateWithFlags(&s1, cudaStreamNonBlocking);
        cudaStreamCreateWithFlags(&s2, cudaStreamNonBlocking);
        cudaEventCreateWithFlags(&evRoot, cudaEventDisableTiming);
        cudaEventCreateWithFlags(&evPrep, cudaEventDisableTiming);
        cudaEventCreateWithFlags(&evCSR,  cudaEventDisableTiming);
        cudaEventCreateWithFlags(&evDisp, cudaEventDisableTiming);
        cudaFuncSetAttribute(k_scan, cudaFuncAttributeMaxDynamicSharedMemorySize,
                             (NMAX + 1) * (int)sizeof(int));
        cudaFuncSetAttribute(k_gemm_h<true, true>,
                             cudaFuncAttributeMaxDynamicSharedMemorySize, GEMM_SMEM);
        cudaFuncSetAttribute(k_gemm_h<false, false>,
                             cudaFuncAttributeMaxDynamicSharedMemorySize, GEMM_SMEM);
        inited = true;
    }

    void *p_xlr, *p_h;
    __half *p_WlrT, *p_WoutT;
    float *p_blr;
    cudaGetSymbolAddress(&p_xlr, d_x_lr);
    cudaGetSymbolAddress(&p_h,   d_h);
    cudaGetSymbolAddress((void**)&p_WlrT,  d_WlrT);
    cudaGetSymbolAddress((void**)&p_WoutT, d_WoutT);
    cudaGetSymbolAddress((void**)&p_blr,   d_blr);

    float* out_logits = (float*)d_out;
    float* out_disp   = (float*)d_out + (size_t)N * OUTD;

    cudaEventRecord(evRoot, 0);
    cudaStreamWaitEvent(s1, evRoot, 0);

    // launches 1-2: main prep
    k_ct<<<(N + 255) / 256, 256>>>(onehot, N);
    k_asm<<<(2 * HIDDEN * EMBED + 255) / 256, 256>>>(W_l, b_l, W_r, b_r, W_out, disper);
    cudaEventRecord(evPrep, 0);

    // launch 3: CSR zero on s1
    k_zero<<<(N + 255) / 256, 256, 0, s1>>>(N);

    // launch 4 (ncu-profiled slot): fused embedding + dual transform GEMM
    k_gemm_h<true, true><<<dim3((N + 127) / 128, (2 * HIDDEN) / 128), 256, GEMM_SMEM>>>(
        N, EMBED, 2 * HIDDEN, nullptr, p_WlrT, p_blr, p_xlr, W_embed, b_embed, lds);

    // launches 5-7: rest of CSR build on s1
    k_hist<<<(E + 255) / 256, 256, 0, s1>>>(ei, E);
    k_scan<<<1, 1024, scan_smem, s1>>>(N);
    k_scatter<<<(E + 255) / 256, 256, 0, s1>>>(ei, E);
    cudaEventRecord(evCSR, s1);

    // launch 8: dispersion output on s2
    cudaStreamWaitEvent(s2, evPrep, 0);
    k_disp<<<(N * (OUTD / 4) + 255) / 256, 256, 0, s2>>>(out_disp, N);
    cudaEventRecord(evDisp, s2);

    // launch 9: fused edge phase (after CSR join)
    cudaStreamWaitEvent(0, evCSR, 0);
    k_edge<<<(N * 32 + 255) / 256, 256>>>(att, gbias, N);

    // launch 10: output head
    k_gemm_h<false, false><<<dim3((N + 127) / 128, OUTD / 128), 256, GEMM_SMEM>>>(
        N, HIDDEN, OUTD, (const __half*)p_h, p_WoutT, b_out, out_logits,
        nullptr, nullptr, nullptr);

    cudaStreamWaitEvent(0, evDisp, 0);
}